// round 12
// baseline (speedup 1.0000x reference)
#include <cuda_runtime.h>
#include <cuda_bf16.h>
#include <stdint.h>

typedef __nv_bfloat16 bf16;

// ---------------- static device scratch (no runtime allocation) -------------
__device__ bf16 d_embB[(size_t)50000 * 304];   // padded bf16 embedding [v][304]
__device__ bf16 d_WxT[(size_t)2048 * 304];     // Wx transposed [n][304] bf16
__device__ bf16 d_WhB[512 * 2048];
__device__ bf16 d_W1B[512 * 1024];
__device__ bf16 d_W2B[1024 * 1024];
__device__ bf16 d_xg[(size_t)32768 * 2048];    // time-major [t][b][g]
__device__ bf16 d_h[2][64 * 512];              // ping-pong h
__device__ unsigned int d_maskB[64 * 16];      // bit-packed mask [b][t/32]
__device__ bf16 d_a1[64 * 1024];
__device__ bf16 d_a2[64 * 1024];
__device__ unsigned int d_steps[512];          // per-step release flags
__device__ unsigned int d_bar;                 // arrival counter (monotonic)

// ---------------- helpers ---------------------------------------------------
__device__ __forceinline__ uint32_t pack_bf2(float a, float b) {
    __nv_bfloat162 t = __floats2bfloat162_rn(a, b);
    return *reinterpret_cast<uint32_t*>(&t);
}

__device__ __forceinline__ void mma16816(float* c, const uint32_t* a, const uint32_t* b) {
    asm volatile(
        "mma.sync.aligned.m16n8k16.row.col.f32.bf16.bf16.f32 "
        "{%0,%1,%2,%3},{%4,%5,%6,%7},{%8,%9},{%0,%1,%2,%3};"
        : "+f"(c[0]), "+f"(c[1]), "+f"(c[2]), "+f"(c[3])
        : "r"(a[0]), "r"(a[1]), "r"(a[2]), "r"(a[3]), "r"(b[0]), "r"(b[1]));
}

__device__ __forceinline__ void ldsm4(uint32_t* r, uint32_t addr) {
    asm volatile("ldmatrix.sync.aligned.m8n8.x4.shared.b16 {%0,%1,%2,%3}, [%4];"
                 : "=r"(r[0]), "=r"(r[1]), "=r"(r[2]), "=r"(r[3]) : "r"(addr));
}

__device__ __forceinline__ uint32_t s2u(const void* p) {
    return (uint32_t)__cvta_generic_to_shared(p);
}

__device__ __forceinline__ void cp16(uint32_t dst, const void* src) {
    asm volatile("cp.async.cg.shared.global [%0], [%1], 16;" :: "r"(dst), "l"(src));
}

__device__ __forceinline__ void cp_wait_all() {
    asm volatile("cp.async.commit_group;\ncp.async.wait_group 0;" ::: "memory");
}

__device__ __forceinline__ void st_release(unsigned int* p, unsigned int v) {
    asm volatile("st.global.release.gpu.b32 [%0], %1;" :: "l"(p), "r"(v) : "memory");
}

__device__ __forceinline__ unsigned int ld_acquire(const unsigned int* p) {
    unsigned int v;
    asm volatile("ld.global.acquire.gpu.b32 %0, [%1];" : "=r"(v) : "l"(p) : "memory");
    return v;
}

// ---------------- launch 0: vectorized embedding conversion ------------------
__global__ void k_cvt_emb(const float* __restrict__ e) {
    int i = blockIdx.x * 256 + threadIdx.x;
    if (i >= 50000 * 38) return;
    int row = i / 38, j = i - 38 * row;
    const float* src = e + (size_t)row * 300 + j * 8;
    float4 lo = *reinterpret_cast<const float4*>(src);
    float4 hi = make_float4(0.f, 0.f, 0.f, 0.f);
    if (j < 37) hi = *reinterpret_cast<const float4*>(src + 4);
    uint4 o;
    o.x = pack_bf2(lo.x, lo.y); o.y = pack_bf2(lo.z, lo.w);
    o.z = pack_bf2(hi.x, hi.y); o.w = pack_bf2(hi.z, hi.w);
    *reinterpret_cast<uint4*>(&d_embB[(size_t)row * 304 + j * 8]) = o;
}

// ---------------- launch 1: everything else (WxT, Wh/W1/W2, mask, zero) -----
__global__ void k_cvt_rest(const float* __restrict__ Wx, const float* __restrict__ Wh,
                           const float* __restrict__ W1, const float* __restrict__ W2,
                           const int* __restrict__ tokens) {
    int i = blockIdx.x * 256 + threadIdx.x;
    if (i < 622592) {                       // WxT (transpose, scalar)
        int n = i / 304, k = i - 304 * n;
        d_WxT[i] = __float2bfloat16(k < 300 ? Wx[(size_t)k * 2048 + n] : 0.f);
    } else if (i < 950272) {                // Wh/W1/W2, 8 elements per thread
        int j = i - 622592;
        const float* src; bf16* dst;
        if (j < 131072)      { src = Wh + (size_t)j * 8;            dst = d_WhB + (size_t)j * 8; }
        else if (j < 196608) { src = W1 + (size_t)(j - 131072) * 8; dst = d_W1B + (size_t)(j - 131072) * 8; }
        else                 { src = W2 + (size_t)(j - 196608) * 8; dst = d_W2B + (size_t)(j - 196608) * 8; }
        float4 lo = *reinterpret_cast<const float4*>(src);
        float4 hi = *reinterpret_cast<const float4*>(src + 4);
        uint4 o;
        o.x = pack_bf2(lo.x, lo.y); o.y = pack_bf2(lo.z, lo.w);
        o.z = pack_bf2(hi.x, hi.y); o.w = pack_bf2(hi.z, hi.w);
        *reinterpret_cast<uint4*>(dst) = o;
    } else if (i < 951296) {                // bit-packed mask [b][w]
        int j = i - 950272;                 // j < 1024
        int b = j >> 4, w = j & 15;
        unsigned int bits = 0u;
        const int* tp = tokens + b * 512 + w * 32;
        #pragma unroll 8
        for (int q = 0; q < 32; q++)
            if (tp[q] != 0) bits |= (1u << q);
        d_maskB[j] = bits;
    } else if (i < 955392) {                // zero h[0]
        uint4 z = make_uint4(0u, 0u, 0u, 0u);
        reinterpret_cast<uint4*>(d_h[0])[i - 951296] = z;
    } else if (i < 955904) {                // zero step flags
        d_steps[i - 955392] = 0u;
    } else if (i == 955904) {               // zero arrival counter
        d_bar = 0u;
    }
}

// ---------------- launch 2: Phase A  xg = gather(emb)@Wx + b ----------------
__global__ void __launch_bounds__(256) k_phaseA(const int* __restrict__ tokens,
                                                const float* __restrict__ bias) {
    extern __shared__ bf16 smA[];
    bf16* As = smA;                 // 128 x 312
    bf16* Bs = smA + 128 * 312;     // 128 x 312
    __shared__ int stok[128];

    int tid = threadIdx.x;
    int n0 = blockIdx.x * 128;
    int m0 = blockIdx.y * 128;
    if (tid < 128) stok[tid] = tokens[m0 + tid];
    __syncthreads();

    {
        int row = tid >> 1, half = tid & 1;
        const bf16* sa = &d_embB[(size_t)stok[row] * 304 + half * 152];
        uint32_t da = s2u(&As[row * 312 + half * 152]);
        const bf16* sb = &d_WxT[(size_t)(n0 + row) * 304 + half * 152];
        uint32_t db = s2u(&Bs[row * 312 + half * 152]);
        #pragma unroll
        for (int j = 0; j < 19; j++) {
            cp16(da + j * 16, sa + j * 8);
            cp16(db + j * 16, sb + j * 8);
        }
        cp_wait_all();
    }
    __syncthreads();

    int w = tid >> 5, lane = tid & 31, g = lane >> 2, tq = lane & 3;
    int wm = (w >> 2) * 64;
    int wn = (w & 3) * 32;
    int lr = lane & 7, lm = lane >> 3;

    uint32_t aab[4], bab[2];
    #pragma unroll
    for (int mo = 0; mo < 4; mo++)
        aab[mo] = s2u(&As[(wm + mo * 16 + lr + (lm & 1) * 8) * 312 + (lm >> 1) * 8]);
    bab[0] = s2u(&Bs[(wn +      lr + (lm >> 1) * 8) * 312 + (lm & 1) * 8]);
    bab[1] = s2u(&Bs[(wn + 16 + lr + (lm >> 1) * 8) * 312 + (lm & 1) * 8]);

    float C[4][4][4];
    #pragma unroll
    for (int a = 0; a < 4; a++)
        #pragma unroll
        for (int b2 = 0; b2 < 4; b2++)
            #pragma unroll
            for (int c = 0; c < 4; c++) C[a][b2][c] = 0.f;

    #pragma unroll 1
    for (int ks = 0; ks < 19; ks++) {
        uint32_t B8[8];
        ldsm4(B8, bab[0] + ks * 32);
        ldsm4(B8 + 4, bab[1] + ks * 32);
        #pragma unroll
        for (int mo = 0; mo < 4; mo++) {
            uint32_t A4[4];
            ldsm4(A4, aab[mo] + ks * 32);
            mma16816(C[mo][0], A4, B8 + 0);
            mma16816(C[mo][1], A4, B8 + 2);
            mma16816(C[mo][2], A4, B8 + 4);
            mma16816(C[mo][3], A4, B8 + 6);
        }
    }
    __syncthreads();   // done reading As/Bs; reuse As region for C staging

    // stage C tile (+bias) in SMEM: 128 rows x 68 uint32 (pitch-68)
    uint32_t* Cs = reinterpret_cast<uint32_t*>(smA);
    #pragma unroll
    for (int mo = 0; mo < 4; mo++) {
        #pragma unroll
        for (int no = 0; no < 4; no++) {
            int gcol = n0 + wn + no * 8 + 2 * tq;
            float b0 = bias[gcol], b1v = bias[gcol + 1];
            int r1 = wm + mo * 16 + g;
            int c = (wn >> 1) + no * 4 + tq;
            Cs[r1 * 68 + c]       = pack_bf2(C[mo][no][0] + b0, C[mo][no][1] + b1v);
            Cs[(r1 + 8) * 68 + c] = pack_bf2(C[mo][no][2] + b0, C[mo][no][3] + b1v);
        }
    }
    __syncthreads();

    // coalesced write-out: warp covers 2 rows x 256B
    {
        int r = tid >> 4, c16 = tid & 15;
        #pragma unroll
        for (int p = 0; p < 8; p++) {
            int row = p * 16 + r;
            int m = m0 + row;
            int t = m & 511, bb = m >> 9;
            uint4 v = *reinterpret_cast<uint4*>(&Cs[row * 68 + c16 * 4]);
            *reinterpret_cast<uint4*>(
                &d_xg[((size_t)(t * 64 + bb)) * 2048 + n0 + c16 * 8]) = v;
        }
    }
}

// ---------------- launch 3: recurrence ---------------------------------------
// 64 persistent CTAs x 8 units, 256 threads (8 warps: 4 m-tiles x 2 K-halves)
// Halved h-broadcast traffic (4MB/step vs 8MB at 128 CTAs).
// dyn SMEM: Ws 32x520 bf16 (33280) | hs 64x520 bf16 (66560) |
//           gf 2x32x65 fp32 (16640) | maskS 1024 u32 (4096) -> 120576 B
__global__ void __launch_bounds__(256, 1) k_recur() {
    extern __shared__ char sm[];
    bf16* Ws = reinterpret_cast<bf16*>(sm);
    bf16* hs = reinterpret_cast<bf16*>(sm + 33280);
    float* gf = reinterpret_cast<float*>(sm + 99840);
    uint32_t* maskS = reinterpret_cast<uint32_t*>(sm + 116480);

    int tid = threadIdx.x, cta = blockIdx.x;
    int u0 = cta * 8;

    // Ws: 32 rows n (gate=n>>3, unit=u0+(n&7)) x K=512
    for (int i = tid; i < 32 * 512; i += 256) {
        int n = i & 31, k = i >> 5;
        Ws[n * 520 + k] = d_WhB[k * 2048 + (n >> 3) * 512 + u0 + (n & 7)];
    }
    // bit-packed mask, loaded once
    for (int i = tid; i < 1024; i += 256) maskS[i] = d_maskB[i];

    int w = tid >> 5, lane = tid & 31, g = lane >> 2, tq = lane & 3;
    int mt = w & 3, kh = w >> 2;            // 4 m-tiles x 2 K-halves
    int lr = lane & 7, lm = lane >> 3;
    uint32_t a_base = s2u(&hs[(mt * 16 + lr + (lm & 1) * 8) * 520 + (lm >> 1) * 8 + kh * 256]);
    uint32_t b_base0 = s2u(&Ws[(lr + (lm >> 1) * 8) * 520 + (lm & 1) * 8 + kh * 256]);
    uint32_t b_base1 = s2u(&Ws[(16 + lr + (lm >> 1) * 8) * 520 + (lm & 1) * 8 + kh * 256]);

    int eb = tid >> 2, eu = tid & 3;        // epilogue: batch eb, units eu, eu+4
    float cst[2] = {0.f, 0.f};
    __syncthreads();

    for (int t = 0; t < 512; t++) {
        // xg prefetch for both unit pairs (consumed post-MMA)
        const bf16* xb = d_xg + (size_t)t * 131072 + eb * 2048 + u0;
        bf16 xv[2][4];
        #pragma unroll
        for (int p = 0; p < 2; p++) {
            const bf16* xr = xb + eu + p * 4;
            xv[p][0] = xr[0]; xv[p][1] = xr[512]; xv[p][2] = xr[1024]; xv[p][3] = xr[1536];
        }

        // stage h (64x512 bf16, 64KB) via uint4
        const bf16* hsrc = d_h[t & 1];
        #pragma unroll
        for (int j = 0; j < 16; j++) {
            int i = j * 256 + tid;
            int row = i >> 6, qc = i & 63;
            *reinterpret_cast<uint4*>(&hs[row * 520 + qc * 8]) =
                __ldcg(reinterpret_cast<const uint4*>(&hsrc[row * 512 + qc * 8]));
        }
        __syncthreads();

        float C0[4] = {0.f, 0.f, 0.f, 0.f};
        float C1[4] = {0.f, 0.f, 0.f, 0.f};
        float C2[4] = {0.f, 0.f, 0.f, 0.f};
        float C3[4] = {0.f, 0.f, 0.f, 0.f};
        #pragma unroll 8
        for (int ks = 0; ks < 16; ks++) {
            uint32_t A4[4], B4[4], B8[4];
            ldsm4(A4, a_base + ks * 32);
            ldsm4(B4, b_base0 + ks * 32);
            ldsm4(B8, b_base1 + ks * 32);
            mma16816(C0, A4, B4);
            mma16816(C1, A4, B4 + 2);
            mma16816(C2, A4, B8);
            mma16816(C3, A4, B8 + 2);
        }
        {
            float* gfp = gf + kh * 2080 + mt * 16 + g;
            gfp[(2 * tq) * 65]          = C0[0];
            gfp[(2 * tq + 1) * 65]      = C0[1];
            gfp[(2 * tq) * 65 + 8]      = C0[2];
            gfp[(2 * tq + 1) * 65 + 8]  = C0[3];
            gfp[(8 + 2 * tq) * 65]          = C1[0];
            gfp[(8 + 2 * tq + 1) * 65]      = C1[1];
            gfp[(8 + 2 * tq) * 65 + 8]      = C1[2];
            gfp[(8 + 2 * tq + 1) * 65 + 8]  = C1[3];
            gfp[(16 + 2 * tq) * 65]         = C2[0];
            gfp[(16 + 2 * tq + 1) * 65]     = C2[1];
            gfp[(16 + 2 * tq) * 65 + 8]     = C2[2];
            gfp[(16 + 2 * tq + 1) * 65 + 8] = C2[3];
            gfp[(24 + 2 * tq) * 65]         = C3[0];
            gfp[(24 + 2 * tq + 1) * 65]     = C3[1];
            gfp[(24 + 2 * tq) * 65 + 8]     = C3[2];
            gfp[(24 + 2 * tq + 1) * 65 + 8] = C3[3];
        }
        __syncthreads();

        // epilogue: thread = (batch eb, units eu and eu+4); sum two K-halves
        bf16* hdst = d_h[(t + 1) & 1];
        bool act = (maskS[eb * 16 + (t >> 5)] >> (t & 31)) & 1u;
        #pragma unroll
        for (int p = 0; p < 2; p++) {
            int u = eu + p * 4;
            float gi  = gf[(u) * 65 + eb]       + gf[2080 + (u) * 65 + eb]       + __bfloat162float(xv[p][0]);
            float gff = gf[(8 + u) * 65 + eb]   + gf[2080 + (8 + u) * 65 + eb]   + __bfloat162float(xv[p][1]);
            float gc  = gf[(16 + u) * 65 + eb]  + gf[2080 + (16 + u) * 65 + eb]  + __bfloat162float(xv[p][2]);
            float go  = gf[(24 + u) * 65 + eb]  + gf[2080 + (24 + u) * 65 + eb]  + __bfloat162float(xv[p][3]);
            float si = 1.f / (1.f + __expf(-gi));
            float sf = 1.f / (1.f + __expf(-gff));
            float so = 1.f / (1.f + __expf(-go));
            float cn = sf * cst[p] + si * fmaxf(gc, 0.f);
            float hn = so * fmaxf(cn, 0.f);
            float hout;
            if (act) { cst[p] = cn; hout = hn; }
            else { hout = __bfloat162float(hs[eb * 520 + u0 + u]); }
            hdst[eb * 512 + u0 + u] = __float2bfloat16(hout);
        }
        __syncthreads();   // all h stores issued, hs/gf reusable

        if (t < 511) {
            // two-level barrier: atomic arrivals, cta0 polls, broadcast flag
            if (tid == 0) {
                __threadfence();
                atomicAdd(&d_bar, 1u);
                if (cta == 0) {
                    unsigned tgt = 64u * (unsigned)(t + 1);
                    while (ld_acquire(&d_bar) < tgt) { }
                    st_release(&d_steps[t], 1u);
                } else {
                    while (ld_acquire(&d_steps[t]) == 0u) { }
                }
            }
            __syncthreads();
        }
    }
}

// ---------------- MLP layers -------------------------------------------------
__global__ void __launch_bounds__(256) k_mlp(int mode, const float* __restrict__ bias) {
    const bf16* A; const bf16* W; bf16* out; int K;
    if (mode == 0) { A = d_h[0]; W = d_W1B; out = d_a1; K = 512; }
    else           { A = d_a1;   W = d_W2B; out = d_a2; K = 1024; }
    int tid = threadIdx.x;
    int col = blockIdx.x * 64 + (tid & 63);
    int rb = blockIdx.y * 16 + (tid >> 6);
    float acc[4] = {0.f, 0.f, 0.f, 0.f};
    for (int k = 0; k < K; k++) {
        float wv = __bfloat162float(W[k * 1024 + col]);
        #pragma unroll
        for (int j = 0; j < 4; j++)
            acc[j] += __bfloat162float(A[(rb + 4 * j) * K + k]) * wv;
    }
    float bv = bias[col];
    #pragma unroll
    for (int j = 0; j < 4; j++)
        out[(rb + 4 * j) * 1024 + col] = __float2bfloat16(fmaxf(acc[j] + bv, 0.f));
}

// ---------------- logits + softmax ------------------------------------------
__global__ void __launch_bounds__(128) k_out(const float* __restrict__ Wo,
                                             const float* __restrict__ bo,
                                             float* __restrict__ out) {
    __shared__ float red[128 * 20];
    int row = blockIdx.x, tid = threadIdx.x;
    float p[20];
    #pragma unroll
    for (int c = 0; c < 20; c++) p[c] = 0.f;
    for (int k = tid; k < 1024; k += 128) {
        float a = __bfloat162float(d_a2[row * 1024 + k]);
        #pragma unroll
        for (int c = 0; c < 20; c++) p[c] += a * Wo[k * 20 + c];
    }
    #pragma unroll
    for (int c = 0; c < 20; c++) red[tid * 20 + c] = p[c];
    __syncthreads();
    for (int s = 64; s > 0; s >>= 1) {
        if (tid < s) {
            #pragma unroll
            for (int c = 0; c < 20; c++) red[tid * 20 + c] += red[(tid + s) * 20 + c];
        }
        __syncthreads();
    }
    if (tid == 0) {
        float l[20], mx = -1e30f, ss = 0.f;
        #pragma unroll
        for (int c = 0; c < 20; c++) { l[c] = red[c] + bo[c]; mx = fmaxf(mx, l[c]); }
        #pragma unroll
        for (int c = 0; c < 20; c++) { l[c] = __expf(l[c] - mx); ss += l[c]; }
        #pragma unroll
        for (int c = 0; c < 20; c++) out[row * 20 + c] = l[c] / ss;
    }
}

// ---------------- launcher ---------------------------------------------------
extern "C" void kernel_launch(void* const* d_in, const int* in_sizes, int n_in,
                              void* d_out, int out_size) {
    const int*   tokens = (const int*)d_in[0];
    const float* emb = (const float*)d_in[1];
    const float* Wx  = (const float*)d_in[2];
    const float* Wh  = (const float*)d_in[3];
    const float* b   = (const float*)d_in[4];
    const float* W1  = (const float*)d_in[5];
    const float* b1  = (const float*)d_in[6];
    const float* W2  = (const float*)d_in[7];
    const float* b2  = (const float*)d_in[8];
    const float* Wo  = (const float*)d_in[9];
    const float* bo  = (const float*)d_in[10];
    float* out = (float*)d_out;

    cudaFuncSetAttribute(k_phaseA, cudaFuncAttributeMaxDynamicSharedMemorySize, 159744);
    cudaFuncSetAttribute(k_recur, cudaFuncAttributeMaxDynamicSharedMemorySize, 120576);

    k_cvt_emb<<<(50000 * 38 + 255) / 256, 256>>>(emb);                          // 0
    k_cvt_rest<<<(955905 + 255) / 256, 256>>>(Wx, Wh, W1, W2, tokens);          // 1
    k_phaseA<<<dim3(16, 256), 256, 159744>>>(tokens, b);                        // 2
    k_recur<<<64, 256, 120576>>>();                                             // 3
    k_mlp<<<dim3(16, 4), 256>>>(0, b1);                                         // 4
    k_mlp<<<dim3(16, 4), 256>>>(1, b2);                                         // 5
    k_out<<<64, 128>>>(Wo, bo, out);                                            // 6
}

// round 13
// speedup vs baseline: 1.1147x; 1.1147x over previous
#include <cuda_runtime.h>
#include <cuda_bf16.h>
#include <stdint.h>

typedef __nv_bfloat16 bf16;

// ---------------- static device scratch (no runtime allocation) -------------
__device__ bf16 d_embB[(size_t)50000 * 304];   // padded bf16 embedding [v][304]
__device__ bf16 d_WxT[(size_t)2048 * 304];     // Wx transposed [n][304] bf16
__device__ bf16 d_WhB[512 * 2048];
__device__ bf16 d_W1B[512 * 1024];
__device__ bf16 d_W2B[1024 * 1024];
__device__ bf16 d_xg[(size_t)32768 * 2048];    // time-major [t][b][g]
__device__ bf16 d_h[2][64 * 512];              // ping-pong h
__device__ unsigned int d_maskB[64 * 16];      // bit-packed mask [b][t/32]
__device__ bf16 d_a1[64 * 1024];
__device__ bf16 d_a2[64 * 1024];
__device__ unsigned int d_stepsG[4 * 512];     // per-group per-step release flags
__device__ unsigned int d_bar4[128];           // 4 group counters, 128B apart

// ---------------- helpers ---------------------------------------------------
__device__ __forceinline__ uint32_t pack_bf2(float a, float b) {
    __nv_bfloat162 t = __floats2bfloat162_rn(a, b);
    return *reinterpret_cast<uint32_t*>(&t);
}

__device__ __forceinline__ void mma16816(float* c, const uint32_t* a, const uint32_t* b) {
    asm volatile(
        "mma.sync.aligned.m16n8k16.row.col.f32.bf16.bf16.f32 "
        "{%0,%1,%2,%3},{%4,%5,%6,%7},{%8,%9},{%0,%1,%2,%3};"
        : "+f"(c[0]), "+f"(c[1]), "+f"(c[2]), "+f"(c[3])
        : "r"(a[0]), "r"(a[1]), "r"(a[2]), "r"(a[3]), "r"(b[0]), "r"(b[1]));
}

__device__ __forceinline__ void ldsm4(uint32_t* r, uint32_t addr) {
    asm volatile("ldmatrix.sync.aligned.m8n8.x4.shared.b16 {%0,%1,%2,%3}, [%4];"
                 : "=r"(r[0]), "=r"(r[1]), "=r"(r[2]), "=r"(r[3]) : "r"(addr));
}

__device__ __forceinline__ uint32_t s2u(const void* p) {
    return (uint32_t)__cvta_generic_to_shared(p);
}

__device__ __forceinline__ void cp16(uint32_t dst, const void* src) {
    asm volatile("cp.async.cg.shared.global [%0], [%1], 16;" :: "r"(dst), "l"(src));
}

__device__ __forceinline__ void cp_wait_all() {
    asm volatile("cp.async.commit_group;\ncp.async.wait_group 0;" ::: "memory");
}

__device__ __forceinline__ void st_release(unsigned int* p, unsigned int v) {
    asm volatile("st.global.release.gpu.b32 [%0], %1;" :: "l"(p), "r"(v) : "memory");
}

__device__ __forceinline__ unsigned int ld_acquire(const unsigned int* p) {
    unsigned int v;
    asm volatile("ld.global.acquire.gpu.b32 %0, [%1];" : "=r"(v) : "l"(p) : "memory");
    return v;
}

// ---------------- launch 0: vectorized embedding conversion ------------------
__global__ void k_cvt_emb(const float* __restrict__ e) {
    int i = blockIdx.x * 256 + threadIdx.x;
    if (i >= 50000 * 38) return;
    int row = i / 38, j = i - 38 * row;
    const float* src = e + (size_t)row * 300 + j * 8;
    float4 lo = *reinterpret_cast<const float4*>(src);
    float4 hi = make_float4(0.f, 0.f, 0.f, 0.f);
    if (j < 37) hi = *reinterpret_cast<const float4*>(src + 4);
    uint4 o;
    o.x = pack_bf2(lo.x, lo.y); o.y = pack_bf2(lo.z, lo.w);
    o.z = pack_bf2(hi.x, hi.y); o.w = pack_bf2(hi.z, hi.w);
    *reinterpret_cast<uint4*>(&d_embB[(size_t)row * 304 + j * 8]) = o;
}

// ---------------- launch 1: everything else (WxT, Wh/W1/W2, mask, zero) -----
__global__ void k_cvt_rest(const float* __restrict__ Wx, const float* __restrict__ Wh,
                           const float* __restrict__ W1, const float* __restrict__ W2,
                           const int* __restrict__ tokens) {
    int i = blockIdx.x * 256 + threadIdx.x;
    if (i < 622592) {                       // WxT (transpose, scalar)
        int n = i / 304, k = i - 304 * n;
        d_WxT[i] = __float2bfloat16(k < 300 ? Wx[(size_t)k * 2048 + n] : 0.f);
    } else if (i < 950272) {                // Wh/W1/W2, 8 elements per thread
        int j = i - 622592;
        const float* src; bf16* dst;
        if (j < 131072)      { src = Wh + (size_t)j * 8;            dst = d_WhB + (size_t)j * 8; }
        else if (j < 196608) { src = W1 + (size_t)(j - 131072) * 8; dst = d_W1B + (size_t)(j - 131072) * 8; }
        else                 { src = W2 + (size_t)(j - 196608) * 8; dst = d_W2B + (size_t)(j - 196608) * 8; }
        float4 lo = *reinterpret_cast<const float4*>(src);
        float4 hi = *reinterpret_cast<const float4*>(src + 4);
        uint4 o;
        o.x = pack_bf2(lo.x, lo.y); o.y = pack_bf2(lo.z, lo.w);
        o.z = pack_bf2(hi.x, hi.y); o.w = pack_bf2(hi.z, hi.w);
        *reinterpret_cast<uint4*>(dst) = o;
    } else if (i < 951296) {                // bit-packed mask [b][w]
        int j = i - 950272;                 // j < 1024
        int b = j >> 4, w = j & 15;
        unsigned int bits = 0u;
        const int* tp = tokens + b * 512 + w * 32;
        #pragma unroll 8
        for (int q = 0; q < 32; q++)
            if (tp[q] != 0) bits |= (1u << q);
        d_maskB[j] = bits;
    } else if (i < 955392) {                // zero h[0]
        uint4 z = make_uint4(0u, 0u, 0u, 0u);
        reinterpret_cast<uint4*>(d_h[0])[i - 951296] = z;
    } else if (i < 957440) {                // zero group step flags (2048)
        d_stepsG[i - 955392] = 0u;
    } else if (i < 957568) {                // zero group counters (128)
        d_bar4[i - 957440] = 0u;
    }
}

// ---------------- launch 2: Phase A  xg = gather(emb)@Wx + b ----------------
__global__ void __launch_bounds__(256) k_phaseA(const int* __restrict__ tokens,
                                                const float* __restrict__ bias) {
    extern __shared__ bf16 smA[];
    bf16* As = smA;                 // 128 x 312
    bf16* Bs = smA + 128 * 312;     // 128 x 312
    __shared__ int stok[128];

    int tid = threadIdx.x;
    int n0 = blockIdx.x * 128;
    int m0 = blockIdx.y * 128;
    if (tid < 128) stok[tid] = tokens[m0 + tid];
    __syncthreads();

    {
        int row = tid >> 1, half = tid & 1;
        const bf16* sa = &d_embB[(size_t)stok[row] * 304 + half * 152];
        uint32_t da = s2u(&As[row * 312 + half * 152]);
        const bf16* sb = &d_WxT[(size_t)(n0 + row) * 304 + half * 152];
        uint32_t db = s2u(&Bs[row * 312 + half * 152]);
        #pragma unroll
        for (int j = 0; j < 19; j++) {
            cp16(da + j * 16, sa + j * 8);
            cp16(db + j * 16, sb + j * 8);
        }
        cp_wait_all();
    }
    __syncthreads();

    int w = tid >> 5, lane = tid & 31, g = lane >> 2, tq = lane & 3;
    int wm = (w >> 2) * 64;
    int wn = (w & 3) * 32;
    int lr = lane & 7, lm = lane >> 3;

    uint32_t aab[4], bab[2];
    #pragma unroll
    for (int mo = 0; mo < 4; mo++)
        aab[mo] = s2u(&As[(wm + mo * 16 + lr + (lm & 1) * 8) * 312 + (lm >> 1) * 8]);
    bab[0] = s2u(&Bs[(wn +      lr + (lm >> 1) * 8) * 312 + (lm & 1) * 8]);
    bab[1] = s2u(&Bs[(wn + 16 + lr + (lm >> 1) * 8) * 312 + (lm & 1) * 8]);

    float C[4][4][4];
    #pragma unroll
    for (int a = 0; a < 4; a++)
        #pragma unroll
        for (int b2 = 0; b2 < 4; b2++)
            #pragma unroll
            for (int c = 0; c < 4; c++) C[a][b2][c] = 0.f;

    #pragma unroll 1
    for (int ks = 0; ks < 19; ks++) {
        uint32_t B8[8];
        ldsm4(B8, bab[0] + ks * 32);
        ldsm4(B8 + 4, bab[1] + ks * 32);
        #pragma unroll
        for (int mo = 0; mo < 4; mo++) {
            uint32_t A4[4];
            ldsm4(A4, aab[mo] + ks * 32);
            mma16816(C[mo][0], A4, B8 + 0);
            mma16816(C[mo][1], A4, B8 + 2);
            mma16816(C[mo][2], A4, B8 + 4);
            mma16816(C[mo][3], A4, B8 + 6);
        }
    }
    __syncthreads();   // done reading As/Bs; reuse As region for C staging

    // stage C tile (+bias) in SMEM: 128 rows x 68 uint32 (pitch-68)
    uint32_t* Cs = reinterpret_cast<uint32_t*>(smA);
    #pragma unroll
    for (int mo = 0; mo < 4; mo++) {
        #pragma unroll
        for (int no = 0; no < 4; no++) {
            int gcol = n0 + wn + no * 8 + 2 * tq;
            float b0 = bias[gcol], b1v = bias[gcol + 1];
            int r1 = wm + mo * 16 + g;
            int c = (wn >> 1) + no * 4 + tq;
            Cs[r1 * 68 + c]       = pack_bf2(C[mo][no][0] + b0, C[mo][no][1] + b1v);
            Cs[(r1 + 8) * 68 + c] = pack_bf2(C[mo][no][2] + b0, C[mo][no][3] + b1v);
        }
    }
    __syncthreads();

    // coalesced write-out: warp covers 2 rows x 256B
    {
        int r = tid >> 4, c16 = tid & 15;
        #pragma unroll
        for (int p = 0; p < 8; p++) {
            int row = p * 16 + r;
            int m = m0 + row;
            int t = m & 511, bb = m >> 9;
            uint4 v = *reinterpret_cast<uint4*>(&Cs[row * 68 + c16 * 4]);
            *reinterpret_cast<uint4*>(
                &d_xg[((size_t)(t * 64 + bb)) * 2048 + n0 + c16 * 8]) = v;
        }
    }
}

// ---------------- launch 3: recurrence, batch-group decomposition ------------
// Grid: 64 CTAs = 4 batch-groups (16 batches) x 16 unit-groups (32 units).
// Groups are fully independent: barrier domain = 16 CTAs, no cross-group sync.
// Per CTA/step: g[16,128] = h_bg[16,512] @ Ws[128,512]^T ; local epilogue.
// SMEM: Ws 128x520 bf16 (133120) | hs 16x520 bf16 (16640) |
//       gf 128x17 f32 (8704) | maskS 256 u32 (1024)  -> 159488 B
__global__ void __launch_bounds__(256, 1) k_recur() {
    extern __shared__ char sm[];
    bf16* Ws = reinterpret_cast<bf16*>(sm);
    bf16* hs = reinterpret_cast<bf16*>(sm + 133120);
    float* gf = reinterpret_cast<float*>(sm + 149760);
    uint32_t* maskS = reinterpret_cast<uint32_t*>(sm + 158464);

    int tid = threadIdx.x, cta = blockIdx.x;
    int bg = cta >> 4, ug = cta & 15;
    int b0 = bg * 16;                 // first batch of group
    int gu0 = ug * 32;                // first unit of this CTA

    // Ws fill: 128 n-rows (gate = n>>5, unit = gu0 + (n&31)) x K=512
    for (int i = tid; i < 128 * 512; i += 256) {
        int n = i & 127, k = i >> 7;
        Ws[n * 520 + k] = d_WhB[k * 2048 + (n >> 5) * 512 + gu0 + (n & 31)];
    }
    // mask words for this group's 16 batches
    if (tid < 256) {
        int lb = tid >> 4, w2 = tid & 15;
        maskS[tid] = d_maskB[(b0 + lb) * 16 + w2];
    }

    int w = tid >> 5, lane = tid & 31, g = lane >> 2, tq = lane & 3;
    int lr = lane & 7, lm = lane >> 3;
    uint32_t a_base = s2u(&hs[(lr + (lm & 1) * 8) * 520 + (lm >> 1) * 8]);
    uint32_t b_base = s2u(&Ws[(w * 16 + lr + (lm >> 1) * 8) * 520 + (lm & 1) * 8]);

    float cst[2] = {0.f, 0.f};
    __syncthreads();

    unsigned int* barp = &d_bar4[bg * 32];
    unsigned int* flagp = &d_stepsG[bg * 512];

    for (int t = 0; t < 512; t++) {
        // xg prefetch for this thread's 2 (batch, unit) items (consumed post-MMA)
        float xv[2][4];
        #pragma unroll
        for (int p = 0; p < 2; p++) {
            int item = tid + p * 256;
            int lb = item >> 5, u = item & 31;
            const bf16* xr = d_xg + (size_t)t * 131072 + (b0 + lb) * 2048 + gu0 + u;
            xv[p][0] = __bfloat162float(__ldcg(xr));
            xv[p][1] = __bfloat162float(__ldcg(xr + 512));
            xv[p][2] = __bfloat162float(__ldcg(xr + 1024));
            xv[p][3] = __bfloat162float(__ldcg(xr + 1536));
        }

        // stage this group's h rows (16 x 512 bf16 = 16KB), 4 uint4 per thread
        const bf16* hsrc = d_h[t & 1];
        #pragma unroll
        for (int j = 0; j < 4; j++) {
            int i = j * 256 + tid;
            int row = i >> 6, qc = i & 63;
            *reinterpret_cast<uint4*>(&hs[row * 520 + qc * 8]) =
                __ldcg(reinterpret_cast<const uint4*>(&hsrc[(b0 + row) * 512 + qc * 8]));
        }
        __syncthreads();

        // MMA: warp owns 16 n-cols, full K=512: 32 iters x (A-ldsm + B-ldsm + 2 mma)
        float C0[4] = {0.f, 0.f, 0.f, 0.f};
        float C1[4] = {0.f, 0.f, 0.f, 0.f};
        #pragma unroll 8
        for (int ks = 0; ks < 32; ks++) {
            uint32_t A4[4], B4[4];
            ldsm4(A4, a_base + ks * 32);
            ldsm4(B4, b_base + ks * 32);
            mma16816(C0, A4, B4);
            mma16816(C1, A4, B4 + 2);
        }
        // store to gf[n][batch], pitch 17
        {
            int nb = w * 16 + 2 * tq;
            gf[(nb) * 17 + g]          = C0[0];
            gf[(nb + 1) * 17 + g]      = C0[1];
            gf[(nb) * 17 + g + 8]      = C0[2];
            gf[(nb + 1) * 17 + g + 8]  = C0[3];
            gf[(nb + 8) * 17 + g]         = C1[0];
            gf[(nb + 9) * 17 + g]         = C1[1];
            gf[(nb + 8) * 17 + g + 8]     = C1[2];
            gf[(nb + 9) * 17 + g + 8]     = C1[3];
        }
        __syncthreads();

        // epilogue: 2 items/thread: (local batch lb, local unit u)
        bf16* hdst = d_h[(t + 1) & 1];
        #pragma unroll
        for (int p = 0; p < 2; p++) {
            int item = tid + p * 256;
            int lb = item >> 5, u = item & 31;
            float gi  = gf[(u) * 17 + lb]        + xv[p][0];
            float gff = gf[(32 + u) * 17 + lb]   + xv[p][1];
            float gc  = gf[(64 + u) * 17 + lb]   + xv[p][2];
            float go  = gf[(96 + u) * 17 + lb]   + xv[p][3];
            float si = 1.f / (1.f + __expf(-gi));
            float sf = 1.f / (1.f + __expf(-gff));
            float so = 1.f / (1.f + __expf(-go));
            float cn = sf * cst[p] + si * fmaxf(gc, 0.f);
            float hn = so * fmaxf(cn, 0.f);
            float hout;
            if ((maskS[lb * 16 + (t >> 5)] >> (t & 31)) & 1u) { cst[p] = cn; hout = hn; }
            else { hout = __bfloat162float(hs[lb * 520 + gu0 + u]); }
            hdst[(b0 + lb) * 512 + gu0 + u] = __float2bfloat16(hout);
        }
        __syncthreads();   // h stores issued; hs/gf reusable

        if (t < 511) {
            // per-group two-level barrier: 16 arrivals, ug0 polls + releases
            if (tid == 0) {
                __threadfence();
                atomicAdd(barp, 1u);
                if (ug == 0) {
                    unsigned tgt = 16u * (unsigned)(t + 1);
                    while (ld_acquire(barp) < tgt) { }
                    st_release(&flagp[t], 1u);
                } else {
                    while (ld_acquire(&flagp[t]) == 0u) { }
                }
            }
            __syncthreads();
        }
    }
}

// ---------------- MLP layers -------------------------------------------------
__global__ void __launch_bounds__(256) k_mlp(int mode, const float* __restrict__ bias) {
    const bf16* A; const bf16* W; bf16* out; int K;
    if (mode == 0) { A = d_h[0]; W = d_W1B; out = d_a1; K = 512; }
    else           { A = d_a1;   W = d_W2B; out = d_a2; K = 1024; }
    int tid = threadIdx.x;
    int col = blockIdx.x * 64 + (tid & 63);
    int rb = blockIdx.y * 16 + (tid >> 6);
    float acc[4] = {0.f, 0.f, 0.f, 0.f};
    for (int k = 0; k < K; k++) {
        float wv = __bfloat162float(W[k * 1024 + col]);
        #pragma unroll
        for (int j = 0; j < 4; j++)
            acc[j] += __bfloat162float(A[(rb + 4 * j) * K + k]) * wv;
    }
    float bv = bias[col];
    #pragma unroll
    for (int j = 0; j < 4; j++)
        out[(rb + 4 * j) * 1024 + col] = __float2bfloat16(fmaxf(acc[j] + bv, 0.f));
}

// ---------------- logits + softmax ------------------------------------------
__global__ void __launch_bounds__(128) k_out(const float* __restrict__ Wo,
                                             const float* __restrict__ bo,
                                             float* __restrict__ out) {
    __shared__ float red[128 * 20];
    int row = blockIdx.x, tid = threadIdx.x;
    float p[20];
    #pragma unroll
    for (int c = 0; c < 20; c++) p[c] = 0.f;
    for (int k = tid; k < 1024; k += 128) {
        float a = __bfloat162float(d_a2[row * 1024 + k]);
        #pragma unroll
        for (int c = 0; c < 20; c++) p[c] += a * Wo[k * 20 + c];
    }
    #pragma unroll
    for (int c = 0; c < 20; c++) red[tid * 20 + c] = p[c];
    __syncthreads();
    for (int s = 64; s > 0; s >>= 1) {
        if (tid < s) {
            #pragma unroll
            for (int c = 0; c < 20; c++) red[tid * 20 + c] += red[(tid + s) * 20 + c];
        }
        __syncthreads();
    }
    if (tid == 0) {
        float l[20], mx = -1e30f, ss = 0.f;
        #pragma unroll
        for (int c = 0; c < 20; c++) { l[c] = red[c] + bo[c]; mx = fmaxf(mx, l[c]); }
        #pragma unroll
        for (int c = 0; c < 20; c++) { l[c] = __expf(l[c] - mx); ss += l[c]; }
        #pragma unroll
        for (int c = 0; c < 20; c++) out[row * 20 + c] = l[c] / ss;
    }
}

// ---------------- launcher ---------------------------------------------------
extern "C" void kernel_launch(void* const* d_in, const int* in_sizes, int n_in,
                              void* d_out, int out_size) {
    const int*   tokens = (const int*)d_in[0];
    const float* emb = (const float*)d_in[1];
    const float* Wx  = (const float*)d_in[2];
    const float* Wh  = (const float*)d_in[3];
    const float* b   = (const float*)d_in[4];
    const float* W1  = (const float*)d_in[5];
    const float* b1  = (const float*)d_in[6];
    const float* W2  = (const float*)d_in[7];
    const float* b2  = (const float*)d_in[8];
    const float* Wo  = (const float*)d_in[9];
    const float* bo  = (const float*)d_in[10];
    float* out = (float*)d_out;

    cudaFuncSetAttribute(k_phaseA, cudaFuncAttributeMaxDynamicSharedMemorySize, 159744);
    cudaFuncSetAttribute(k_recur, cudaFuncAttributeMaxDynamicSharedMemorySize, 159488);

    k_cvt_emb<<<(50000 * 38 + 255) / 256, 256>>>(emb);                          // 0
    k_cvt_rest<<<(957568 + 255) / 256, 256>>>(Wx, Wh, W1, W2, tokens);          // 1
    k_phaseA<<<dim3(16, 256), 256, 159744>>>(tokens, b);                        // 2
    k_recur<<<64, 256, 159488>>>();                                             // 3
    k_mlp<<<dim3(16, 4), 256>>>(0, b1);                                         // 4
    k_mlp<<<dim3(16, 4), 256>>>(1, b2);                                         // 5
    k_out<<<64, 128>>>(Wo, bo, out);                                            // 6
}

// round 14
// speedup vs baseline: 1.3397x; 1.2019x over previous
#include <cuda_runtime.h>
#include <cuda_bf16.h>
#include <stdint.h>

typedef __nv_bfloat16 bf16;

// ---------------- static device scratch (no runtime allocation) -------------
__device__ bf16 d_embB[(size_t)50000 * 304];   // padded bf16 embedding [v][304]
__device__ bf16 d_WxT[(size_t)2048 * 304];     // Wx transposed [n][304] bf16
__device__ bf16 d_WhB[512 * 2048];
__device__ bf16 d_W1B[512 * 1024];
__device__ bf16 d_W2B[1024 * 1024];
__device__ bf16 d_xg[(size_t)32768 * 2048];    // time-major [t][b][g]
__device__ bf16 d_h[2][64 * 512];              // d_h[0] = final h (for MLP)
__device__ unsigned int d_maskB[64 * 16];      // bit-packed mask [b][t/32]
__device__ bf16 d_a1[64 * 1024];
__device__ bf16 d_a2[64 * 1024];
__device__ unsigned int d_stepsG[4 * 512];     // (unused by recur now; kept for cvt)
__device__ unsigned int d_bar4[128];           // (unused by recur now; kept for cvt)

// ---------------- helpers ---------------------------------------------------
__device__ __forceinline__ uint32_t pack_bf2(float a, float b) {
    __nv_bfloat162 t = __floats2bfloat162_rn(a, b);
    return *reinterpret_cast<uint32_t*>(&t);
}

__device__ __forceinline__ void mma16816(float* c, const uint32_t* a, const uint32_t* b) {
    asm volatile(
        "mma.sync.aligned.m16n8k16.row.col.f32.bf16.bf16.f32 "
        "{%0,%1,%2,%3},{%4,%5,%6,%7},{%8,%9},{%0,%1,%2,%3};"
        : "+f"(c[0]), "+f"(c[1]), "+f"(c[2]), "+f"(c[3])
        : "r"(a[0]), "r"(a[1]), "r"(a[2]), "r"(a[3]), "r"(b[0]), "r"(b[1]));
}

__device__ __forceinline__ void ldsm4(uint32_t* r, uint32_t addr) {
    asm volatile("ldmatrix.sync.aligned.m8n8.x4.shared.b16 {%0,%1,%2,%3}, [%4];"
                 : "=r"(r[0]), "=r"(r[1]), "=r"(r[2]), "=r"(r[3]) : "r"(addr));
}

__device__ __forceinline__ uint32_t s2u(const void* p) {
    return (uint32_t)__cvta_generic_to_shared(p);
}

__device__ __forceinline__ void cp16(uint32_t dst, const void* src) {
    asm volatile("cp.async.cg.shared.global [%0], [%1], 16;" :: "r"(dst), "l"(src));
}

__device__ __forceinline__ void cp_wait_all() {
    asm volatile("cp.async.commit_group;\ncp.async.wait_group 0;" ::: "memory");
}

__device__ __forceinline__ void dsm_st_u32(uint32_t laddr, uint32_t rank, uint32_t val) {
    uint32_t pa;
    asm volatile("mapa.shared::cluster.u32 %0, %1, %2;" : "=r"(pa) : "r"(laddr), "r"(rank));
    asm volatile("st.shared::cluster.u32 [%0], %1;" :: "r"(pa), "r"(val) : "memory");
}

// ---------------- launch 0: vectorized embedding conversion ------------------
__global__ void k_cvt_emb(const float* __restrict__ e) {
    int i = blockIdx.x * 256 + threadIdx.x;
    if (i >= 50000 * 38) return;
    int row = i / 38, j = i - 38 * row;
    const float* src = e + (size_t)row * 300 + j * 8;
    float4 lo = *reinterpret_cast<const float4*>(src);
    float4 hi = make_float4(0.f, 0.f, 0.f, 0.f);
    if (j < 37) hi = *reinterpret_cast<const float4*>(src + 4);
    uint4 o;
    o.x = pack_bf2(lo.x, lo.y); o.y = pack_bf2(lo.z, lo.w);
    o.z = pack_bf2(hi.x, hi.y); o.w = pack_bf2(hi.z, hi.w);
    *reinterpret_cast<uint4*>(&d_embB[(size_t)row * 304 + j * 8]) = o;
}

// ---------------- launch 1: everything else (WxT, Wh/W1/W2, mask, zero) -----
__global__ void k_cvt_rest(const float* __restrict__ Wx, const float* __restrict__ Wh,
                           const float* __restrict__ W1, const float* __restrict__ W2,
                           const int* __restrict__ tokens) {
    int i = blockIdx.x * 256 + threadIdx.x;
    if (i < 622592) {                       // WxT (transpose, scalar)
        int n = i / 304, k = i - 304 * n;
        d_WxT[i] = __float2bfloat16(k < 300 ? Wx[(size_t)k * 2048 + n] : 0.f);
    } else if (i < 950272) {                // Wh/W1/W2, 8 elements per thread
        int j = i - 622592;
        const float* src; bf16* dst;
        if (j < 131072)      { src = Wh + (size_t)j * 8;            dst = d_WhB + (size_t)j * 8; }
        else if (j < 196608) { src = W1 + (size_t)(j - 131072) * 8; dst = d_W1B + (size_t)(j - 131072) * 8; }
        else                 { src = W2 + (size_t)(j - 196608) * 8; dst = d_W2B + (size_t)(j - 196608) * 8; }
        float4 lo = *reinterpret_cast<const float4*>(src);
        float4 hi = *reinterpret_cast<const float4*>(src + 4);
        uint4 o;
        o.x = pack_bf2(lo.x, lo.y); o.y = pack_bf2(lo.z, lo.w);
        o.z = pack_bf2(hi.x, hi.y); o.w = pack_bf2(hi.z, hi.w);
        *reinterpret_cast<uint4*>(dst) = o;
    } else if (i < 951296) {                // bit-packed mask [b][w]
        int j = i - 950272;                 // j < 1024
        int b = j >> 4, w = j & 15;
        unsigned int bits = 0u;
        const int* tp = tokens + b * 512 + w * 32;
        #pragma unroll 8
        for (int q = 0; q < 32; q++)
            if (tp[q] != 0) bits |= (1u << q);
        d_maskB[j] = bits;
    } else if (i < 955392) {                // zero h[0]
        uint4 z = make_uint4(0u, 0u, 0u, 0u);
        reinterpret_cast<uint4*>(d_h[0])[i - 951296] = z;
    } else if (i < 957440) {                // zero group step flags (2048)
        d_stepsG[i - 955392] = 0u;
    } else if (i < 957568) {                // zero group counters (128)
        d_bar4[i - 957440] = 0u;
    }
}

// ---------------- launch 2: Phase A  xg = gather(emb)@Wx + b ----------------
__global__ void __launch_bounds__(256) k_phaseA(const int* __restrict__ tokens,
                                                const float* __restrict__ bias) {
    extern __shared__ bf16 smA[];
    bf16* As = smA;                 // 128 x 312
    bf16* Bs = smA + 128 * 312;     // 128 x 312
    __shared__ int stok[128];

    int tid = threadIdx.x;
    int n0 = blockIdx.x * 128;
    int m0 = blockIdx.y * 128;
    if (tid < 128) stok[tid] = tokens[m0 + tid];
    __syncthreads();

    {
        int row = tid >> 1, half = tid & 1;
        const bf16* sa = &d_embB[(size_t)stok[row] * 304 + half * 152];
        uint32_t da = s2u(&As[row * 312 + half * 152]);
        const bf16* sb = &d_WxT[(size_t)(n0 + row) * 304 + half * 152];
        uint32_t db = s2u(&Bs[row * 312 + half * 152]);
        #pragma unroll
        for (int j = 0; j < 19; j++) {
            cp16(da + j * 16, sa + j * 8);
            cp16(db + j * 16, sb + j * 8);
        }
        cp_wait_all();
    }
    __syncthreads();

    int w = tid >> 5, lane = tid & 31, g = lane >> 2, tq = lane & 3;
    int wm = (w >> 2) * 64;
    int wn = (w & 3) * 32;
    int lr = lane & 7, lm = lane >> 3;

    uint32_t aab[4], bab[2];
    #pragma unroll
    for (int mo = 0; mo < 4; mo++)
        aab[mo] = s2u(&As[(wm + mo * 16 + lr + (lm & 1) * 8) * 312 + (lm >> 1) * 8]);
    bab[0] = s2u(&Bs[(wn +      lr + (lm >> 1) * 8) * 312 + (lm & 1) * 8]);
    bab[1] = s2u(&Bs[(wn + 16 + lr + (lm >> 1) * 8) * 312 + (lm & 1) * 8]);

    float C[4][4][4];
    #pragma unroll
    for (int a = 0; a < 4; a++)
        #pragma unroll
        for (int b2 = 0; b2 < 4; b2++)
            #pragma unroll
            for (int c = 0; c < 4; c++) C[a][b2][c] = 0.f;

    #pragma unroll 1
    for (int ks = 0; ks < 19; ks++) {
        uint32_t B8[8];
        ldsm4(B8, bab[0] + ks * 32);
        ldsm4(B8 + 4, bab[1] + ks * 32);
        #pragma unroll
        for (int mo = 0; mo < 4; mo++) {
            uint32_t A4[4];
            ldsm4(A4, aab[mo] + ks * 32);
            mma16816(C[mo][0], A4, B8 + 0);
            mma16816(C[mo][1], A4, B8 + 2);
            mma16816(C[mo][2], A4, B8 + 4);
            mma16816(C[mo][3], A4, B8 + 6);
        }
    }
    __syncthreads();   // done reading As/Bs; reuse As region for C staging

    // stage C tile (+bias) in SMEM: 128 rows x 68 uint32 (pitch-68)
    uint32_t* Cs = reinterpret_cast<uint32_t*>(smA);
    #pragma unroll
    for (int mo = 0; mo < 4; mo++) {
        #pragma unroll
        for (int no = 0; no < 4; no++) {
            int gcol = n0 + wn + no * 8 + 2 * tq;
            float b0 = bias[gcol], b1v = bias[gcol + 1];
            int r1 = wm + mo * 16 + g;
            int c = (wn >> 1) + no * 4 + tq;
            Cs[r1 * 68 + c]       = pack_bf2(C[mo][no][0] + b0, C[mo][no][1] + b1v);
            Cs[(r1 + 8) * 68 + c] = pack_bf2(C[mo][no][2] + b0, C[mo][no][3] + b1v);
        }
    }
    __syncthreads();

    // coalesced write-out: warp covers 2 rows x 256B
    {
        int r = tid >> 4, c16 = tid & 15;
        #pragma unroll
        for (int p = 0; p < 8; p++) {
            int row = p * 16 + r;
            int m = m0 + row;
            int t = m & 511, bb = m >> 9;
            uint4 v = *reinterpret_cast<uint4*>(&Cs[row * 68 + c16 * 4]);
            *reinterpret_cast<uint4*>(
                &d_xg[((size_t)(t * 64 + bb)) * 2048 + n0 + c16 * 8]) = v;
        }
    }
}

// ---------------- launch 3: recurrence, 16-CTA clusters + DSMEM exchange -----
// Grid: 64 CTAs = 4 clusters (batch-groups of 16 batches) x 16 unit-CTAs.
// Per CTA/step: g[16,128] = hs[16,512] @ Ws[128,512]^T ; epilogue pushes its
// 16x32 h-slice into all 16 peers' double-buffered hs via DSMEM; HW cluster
// barrier replaces the global flag/atomic machinery. No global h traffic.
// SMEM: Ws 128x520 bf16 (133120) | hs 2 x 16x520 bf16 (33280) |
//       gf 128x17 f32 (8704) | maskS 256 u32 (1024)  -> 176128 B
__global__ void __launch_bounds__(256, 1) k_recur() {
    extern __shared__ char sm[];
    bf16* Ws  = reinterpret_cast<bf16*>(sm);
    bf16* hsb = reinterpret_cast<bf16*>(sm + 133120);   // hsb + par*8320 elems
    float* gf = reinterpret_cast<float*>(sm + 166400);
    uint32_t* maskS = reinterpret_cast<uint32_t*>(sm + 175104);

    int tid = threadIdx.x, cta = blockIdx.x;
    int bg = cta >> 4;
    uint32_t ug;
    asm("mov.u32 %0, %%cluster_ctarank;" : "=r"(ug));
    int b0 = bg * 16;
    int gu0 = (int)ug * 32;

    // Ws fill: 128 n-rows (gate = n>>5, unit = gu0 + (n&31)) x K=512
    for (int i = tid; i < 128 * 512; i += 256) {
        int n = i & 127, k = i >> 7;
        Ws[n * 520 + k] = d_WhB[k * 2048 + (n >> 5) * 512 + gu0 + (n & 31)];
    }
    // mask words for this group's 16 batches
    {
        int lb = tid >> 4, w2 = tid & 15;
        maskS[tid] = d_maskB[(b0 + lb) * 16 + w2];
    }
    // zero both hs buffers (h0 = 0)
    for (int i = tid; i < 2080; i += 256)
        reinterpret_cast<uint4*>(hsb)[i] = make_uint4(0u, 0u, 0u, 0u);
    __syncthreads();
    asm volatile("barrier.cluster.arrive.aligned;" ::: "memory");
    asm volatile("barrier.cluster.wait.aligned;" ::: "memory");

    int w = tid >> 5, lane = tid & 31, g = lane >> 2, tq = lane & 3;
    int lr = lane & 7, lm = lane >> 3;
    uint32_t a_base0 = s2u(&hsb[(lr + (lm & 1) * 8) * 520 + (lm >> 1) * 8]);
    uint32_t b_base = s2u(&Ws[(w * 16 + lr + (lm >> 1) * 8) * 520 + (lm & 1) * 8]);

    int lb = tid >> 4, up = tid & 15;       // epilogue: batch lb, units 2up,2up+1
    uint32_t hout_l0 = s2u(&hsb[lb * 520 + gu0 + 2 * up]);
    float cst[2] = {0.f, 0.f};

    for (int t = 0; t < 512; t++) {
        int par = t & 1;

        // xg prefetch: one uint32 per gate (units 2up, 2up+1), consumed post-MMA
        const bf16* xr = d_xg + (size_t)t * 131072 + (b0 + lb) * 2048 + gu0 + 2 * up;
        uint32_t xq[4];
        xq[0] = __ldcg(reinterpret_cast<const uint32_t*>(xr));
        xq[1] = __ldcg(reinterpret_cast<const uint32_t*>(xr + 512));
        xq[2] = __ldcg(reinterpret_cast<const uint32_t*>(xr + 1024));
        xq[3] = __ldcg(reinterpret_cast<const uint32_t*>(xr + 1536));

        // MMA: h already resident in hs[par] (DSMEM-delivered)
        uint32_t ab = a_base0 + par * 16640;
        float C0[4] = {0.f, 0.f, 0.f, 0.f};
        float C1[4] = {0.f, 0.f, 0.f, 0.f};
        #pragma unroll 8
        for (int ks = 0; ks < 32; ks++) {
            uint32_t A4[4], B4[4];
            ldsm4(A4, ab + ks * 32);
            ldsm4(B4, b_base + ks * 32);
            mma16816(C0, A4, B4);
            mma16816(C1, A4, B4 + 2);
        }
        {
            int nb = w * 16 + 2 * tq;
            gf[(nb) * 17 + g]         = C0[0];
            gf[(nb + 1) * 17 + g]     = C0[1];
            gf[(nb) * 17 + g + 8]     = C0[2];
            gf[(nb + 1) * 17 + g + 8] = C0[3];
            gf[(nb + 8) * 17 + g]         = C1[0];
            gf[(nb + 9) * 17 + g]         = C1[1];
            gf[(nb + 8) * 17 + g + 8]     = C1[2];
            gf[(nb + 9) * 17 + g + 8]     = C1[3];
        }
        __syncthreads();

        // epilogue: 2 adjacent units for one batch, fully in registers
        bool act = (maskS[lb * 16 + (t >> 5)] >> (t & 31)) & 1u;
        const bf16* xb = reinterpret_cast<const bf16*>(xq);
        bf16 hov[2];
        #pragma unroll
        for (int j = 0; j < 2; j++) {
            int u = 2 * up + j;
            float gi  = gf[(u) * 17 + lb]      + __bfloat162float(xb[j]);
            float gff = gf[(32 + u) * 17 + lb] + __bfloat162float(xb[2 + j]);
            float gc  = gf[(64 + u) * 17 + lb] + __bfloat162float(xb[4 + j]);
            float go  = gf[(96 + u) * 17 + lb] + __bfloat162float(xb[6 + j]);
            float si = 1.f / (1.f + __expf(-gi));
            float sf = 1.f / (1.f + __expf(-gff));
            float so = 1.f / (1.f + __expf(-go));
            float cn = sf * cst[j] + si * fmaxf(gc, 0.f);
            float hn = so * fmaxf(cn, 0.f);
            if (act) { cst[j] = cn; hov[j] = __float2bfloat16(hn); }
            else     { hov[j] = hsb[par * 8320 + lb * 520 + gu0 + 2 * up + j]; }
        }
        uint32_t val = *reinterpret_cast<uint32_t*>(hov);

        if (t < 511) {
            // push slice into all 16 peers' hs[par^1] (incl. self)
            uint32_t laddr = hout_l0 + (par ^ 1) * 16640;
            #pragma unroll
            for (int r = 0; r < 16; r++) dsm_st_u32(laddr, (uint32_t)r, val);
            asm volatile("barrier.cluster.arrive.aligned;" ::: "memory");
            asm volatile("barrier.cluster.wait.aligned;" ::: "memory");
        } else {
            *reinterpret_cast<uint32_t*>(&d_h[0][(b0 + lb) * 512 + gu0 + 2 * up]) = val;
        }
    }
}

// ---------------- MLP layers -------------------------------------------------
__global__ void __launch_bounds__(256) k_mlp(int mode, const float* __restrict__ bias) {
    const bf16* A; const bf16* W; bf16* out; int K;
    if (mode == 0) { A = d_h[0]; W = d_W1B; out = d_a1; K = 512; }
    else           { A = d_a1;   W = d_W2B; out = d_a2; K = 1024; }
    int tid = threadIdx.x;
    int col = blockIdx.x * 64 + (tid & 63);
    int rb = blockIdx.y * 16 + (tid >> 6);
    float acc[4] = {0.f, 0.f, 0.f, 0.f};
    for (int k = 0; k < K; k++) {
        float wv = __bfloat162float(W[k * 1024 + col]);
        #pragma unroll
        for (int j = 0; j < 4; j++)
            acc[j] += __bfloat162float(A[(rb + 4 * j) * K + k]) * wv;
    }
    float bv = bias[col];
    #pragma unroll
    for (int j = 0; j < 4; j++)
        out[(rb + 4 * j) * 1024 + col] = __float2bfloat16(fmaxf(acc[j] + bv, 0.f));
}

// ---------------- logits + softmax ------------------------------------------
__global__ void __launch_bounds__(128) k_out(const float* __restrict__ Wo,
                                             const float* __restrict__ bo,
                                             float* __restrict__ out) {
    __shared__ float red[128 * 20];
    int row = blockIdx.x, tid = threadIdx.x;
    float p[20];
    #pragma unroll
    for (int c = 0; c < 20; c++) p[c] = 0.f;
    for (int k = tid; k < 1024; k += 128) {
        float a = __bfloat162float(d_a2[row * 1024 + k]);
        #pragma unroll
        for (int c = 0; c < 20; c++) p[c] += a * Wo[k * 20 + c];
    }
    #pragma unroll
    for (int c = 0; c < 20; c++) red[tid * 20 + c] = p[c];
    __syncthreads();
    for (int s = 64; s > 0; s >>= 1) {
        if (tid < s) {
            #pragma unroll
            for (int c = 0; c < 20; c++) red[tid * 20 + c] += red[(tid + s) * 20 + c];
        }
        __syncthreads();
    }
    if (tid == 0) {
        float l[20], mx = -1e30f, ss = 0.f;
        #pragma unroll
        for (int c = 0; c < 20; c++) { l[c] = red[c] + bo[c]; mx = fmaxf(mx, l[c]); }
        #pragma unroll
        for (int c = 0; c < 20; c++) { l[c] = __expf(l[c] - mx); ss += l[c]; }
        #pragma unroll
        for (int c = 0; c < 20; c++) out[row * 20 + c] = l[c] / ss;
    }
}

// ---------------- launcher ---------------------------------------------------
extern "C" void kernel_launch(void* const* d_in, const int* in_sizes, int n_in,
                              void* d_out, int out_size) {
    const int*   tokens = (const int*)d_in[0];
    const float* emb = (const float*)d_in[1];
    const float* Wx  = (const float*)d_in[2];
    const float* Wh  = (const float*)d_in[3];
    const float* b   = (const float*)d_in[4];
    const float* W1  = (const float*)d_in[5];
    const float* b1  = (const float*)d_in[6];
    const float* W2  = (const float*)d_in[7];
    const float* b2  = (const float*)d_in[8];
    const float* Wo  = (const float*)d_in[9];
    const float* bo  = (const float*)d_in[10];
    float* out = (float*)d_out;

    cudaFuncSetAttribute(k_phaseA, cudaFuncAttributeMaxDynamicSharedMemorySize, 159744);
    cudaFuncSetAttribute(k_recur, cudaFuncAttributeMaxDynamicSharedMemorySize, 176128);
    cudaFuncSetAttribute(k_recur, cudaFuncAttributeNonPortableClusterSizeAllowed, 1);

    k_cvt_emb<<<(50000 * 38 + 255) / 256, 256>>>(emb);                          // 0
    k_cvt_rest<<<(957568 + 255) / 256, 256>>>(Wx, Wh, W1, W2, tokens);          // 1
    k_phaseA<<<dim3(16, 256), 256, 159744>>>(tokens, b);                        // 2

    {   // 16-CTA clusters: 4 clusters x 16 CTAs
        cudaLaunchConfig_t cfg = {};
        cfg.gridDim = dim3(64, 1, 1);
        cfg.blockDim = dim3(256, 1, 1);
        cfg.dynamicSmemBytes = 176128;
        cudaLaunchAttribute attrs[1];
        attrs[0].id = cudaLaunchAttributeClusterDimension;
        attrs[0].val.clusterDim.x = 16;
        attrs[0].val.clusterDim.y = 1;
        attrs[0].val.clusterDim.z = 1;
        cfg.attrs = attrs;
        cfg.numAttrs = 1;
        cudaLaunchKernelEx(&cfg, k_recur);                                      // 3
    }

    k_mlp<<<dim3(16, 4), 256>>>(0, b1);                                         // 4
    k_mlp<<<dim3(16, 4), 256>>>(1, b2);                                         // 5
    k_out<<<64, 128>>>(Wo, bo, out);                                            // 6
}

// round 15
// speedup vs baseline: 1.3463x; 1.0049x over previous
#include <cuda_runtime.h>
#include <cuda_bf16.h>
#include <stdint.h>

typedef __nv_bfloat16 bf16;

// ---------------- static device scratch (no runtime allocation) -------------
__device__ bf16 d_embB[(size_t)50000 * 304];   // padded bf16 embedding [v][304]
__device__ bf16 d_WxT[(size_t)2048 * 304];     // Wx transposed [n][304] bf16
__device__ bf16 d_WhB[512 * 2048];
__device__ bf16 d_W1B[512 * 1024];
__device__ bf16 d_W2B[1024 * 1024];
__device__ bf16 d_xg[(size_t)32768 * 2048];    // time-major [t][b][g]
__device__ bf16 d_h[2][64 * 512];              // d_h[0] = final h (for MLP)
__device__ unsigned int d_maskB[64 * 16];      // bit-packed mask [b][t/32]
__device__ bf16 d_a1[64 * 1024];
__device__ bf16 d_a2[64 * 1024];
__device__ unsigned int d_stepsG[4 * 512];     // (unused by recur now; kept for cvt)
__device__ unsigned int d_bar4[128];           // (unused by recur now; kept for cvt)

// ---------------- helpers ---------------------------------------------------
__device__ __forceinline__ uint32_t pack_bf2(float a, float b) {
    __nv_bfloat162 t = __floats2bfloat162_rn(a, b);
    return *reinterpret_cast<uint32_t*>(&t);
}

__device__ __forceinline__ void mma16816(float* c, const uint32_t* a, const uint32_t* b) {
    asm volatile(
        "mma.sync.aligned.m16n8k16.row.col.f32.bf16.bf16.f32 "
        "{%0,%1,%2,%3},{%4,%5,%6,%7},{%8,%9},{%0,%1,%2,%3};"
        : "+f"(c[0]), "+f"(c[1]), "+f"(c[2]), "+f"(c[3])
        : "r"(a[0]), "r"(a[1]), "r"(a[2]), "r"(a[3]), "r"(b[0]), "r"(b[1]));
}

__device__ __forceinline__ void ldsm4(uint32_t* r, uint32_t addr) {
    asm volatile("ldmatrix.sync.aligned.m8n8.x4.shared.b16 {%0,%1,%2,%3}, [%4];"
                 : "=r"(r[0]), "=r"(r[1]), "=r"(r[2]), "=r"(r[3]) : "r"(addr));
}

__device__ __forceinline__ uint32_t s2u(const void* p) {
    return (uint32_t)__cvta_generic_to_shared(p);
}

__device__ __forceinline__ void cp16(uint32_t dst, const void* src) {
    asm volatile("cp.async.cg.shared.global [%0], [%1], 16;" :: "r"(dst), "l"(src));
}

__device__ __forceinline__ void cp_wait_all() {
    asm volatile("cp.async.commit_group;\ncp.async.wait_group 0;" ::: "memory");
}

// vectorized 16B DSMEM store: local smem addr -> same offset in peer `rank`
__device__ __forceinline__ void dsm_st_u128(uint32_t laddr, uint32_t rank, uint4 v) {
    uint32_t pa;
    asm volatile("mapa.shared::cluster.u32 %0, %1, %2;" : "=r"(pa) : "r"(laddr), "r"(rank));
    asm volatile("st.shared::cluster.v4.u32 [%0], {%1,%2,%3,%4};"
                 :: "r"(pa), "r"(v.x), "r"(v.y), "r"(v.z), "r"(v.w) : "memory");
}

// ---------------- launch 0: vectorized embedding conversion ------------------
__global__ void k_cvt_emb(const float* __restrict__ e) {
    int i = blockIdx.x * 256 + threadIdx.x;
    if (i >= 50000 * 38) return;
    int row = i / 38, j = i - 38 * row;
    const float* src = e + (size_t)row * 300 + j * 8;
    float4 lo = *reinterpret_cast<const float4*>(src);
    float4 hi = make_float4(0.f, 0.f, 0.f, 0.f);
    if (j < 37) hi = *reinterpret_cast<const float4*>(src + 4);
    uint4 o;
    o.x = pack_bf2(lo.x, lo.y); o.y = pack_bf2(lo.z, lo.w);
    o.z = pack_bf2(hi.x, hi.y); o.w = pack_bf2(hi.z, hi.w);
    *reinterpret_cast<uint4*>(&d_embB[(size_t)row * 304 + j * 8]) = o;
}

// ---------------- launch 1: everything else (WxT, Wh/W1/W2, mask, zero) -----
__global__ void k_cvt_rest(const float* __restrict__ Wx, const float* __restrict__ Wh,
                           const float* __restrict__ W1, const float* __restrict__ W2,
                           const int* __restrict__ tokens) {
    int i = blockIdx.x * 256 + threadIdx.x;
    if (i < 622592) {                       // WxT (transpose, scalar)
        int n = i / 304, k = i - 304 * n;
        d_WxT[i] = __float2bfloat16(k < 300 ? Wx[(size_t)k * 2048 + n] : 0.f);
    } else if (i < 950272) {                // Wh/W1/W2, 8 elements per thread
        int j = i - 622592;
        const float* src; bf16* dst;
        if (j < 131072)      { src = Wh + (size_t)j * 8;            dst = d_WhB + (size_t)j * 8; }
        else if (j < 196608) { src = W1 + (size_t)(j - 131072) * 8; dst = d_W1B + (size_t)(j - 131072) * 8; }
        else                 { src = W2 + (size_t)(j - 196608) * 8; dst = d_W2B + (size_t)(j - 196608) * 8; }
        float4 lo = *reinterpret_cast<const float4*>(src);
        float4 hi = *reinterpret_cast<const float4*>(src + 4);
        uint4 o;
        o.x = pack_bf2(lo.x, lo.y); o.y = pack_bf2(lo.z, lo.w);
        o.z = pack_bf2(hi.x, hi.y); o.w = pack_bf2(hi.z, hi.w);
        *reinterpret_cast<uint4*>(dst) = o;
    } else if (i < 951296) {                // bit-packed mask [b][w]
        int j = i - 950272;                 // j < 1024
        int b = j >> 4, w = j & 15;
        unsigned int bits = 0u;
        const int* tp = tokens + b * 512 + w * 32;
        #pragma unroll 8
        for (int q = 0; q < 32; q++)
            if (tp[q] != 0) bits |= (1u << q);
        d_maskB[j] = bits;
    } else if (i < 955392) {                // zero h[0]
        uint4 z = make_uint4(0u, 0u, 0u, 0u);
        reinterpret_cast<uint4*>(d_h[0])[i - 951296] = z;
    } else if (i < 957440) {                // zero group step flags (2048)
        d_stepsG[i - 955392] = 0u;
    } else if (i < 957568) {                // zero group counters (128)
        d_bar4[i - 957440] = 0u;
    }
}

// ---------------- launch 2: Phase A  xg = gather(emb)@Wx + b ----------------
__global__ void __launch_bounds__(256) k_phaseA(const int* __restrict__ tokens,
                                                const float* __restrict__ bias) {
    extern __shared__ bf16 smA[];
    bf16* As = smA;                 // 128 x 312
    bf16* Bs = smA + 128 * 312;     // 128 x 312
    __shared__ int stok[128];

    int tid = threadIdx.x;
    int n0 = blockIdx.x * 128;
    int m0 = blockIdx.y * 128;
    if (tid < 128) stok[tid] = tokens[m0 + tid];
    __syncthreads();

    {
        int row = tid >> 1, half = tid & 1;
        const bf16* sa = &d_embB[(size_t)stok[row] * 304 + half * 152];
        uint32_t da = s2u(&As[row * 312 + half * 152]);
        const bf16* sb = &d_WxT[(size_t)(n0 + row) * 304 + half * 152];
        uint32_t db = s2u(&Bs[row * 312 + half * 152]);
        #pragma unroll
        for (int j = 0; j < 19; j++) {
            cp16(da + j * 16, sa + j * 8);
            cp16(db + j * 16, sb + j * 8);
        }
        cp_wait_all();
    }
    __syncthreads();

    int w = tid >> 5, lane = tid & 31, g = lane >> 2, tq = lane & 3;
    int wm = (w >> 2) * 64;
    int wn = (w & 3) * 32;
    int lr = lane & 7, lm = lane >> 3;

    uint32_t aab[4], bab[2];
    #pragma unroll
    for (int mo = 0; mo < 4; mo++)
        aab[mo] = s2u(&As[(wm + mo * 16 + lr + (lm & 1) * 8) * 312 + (lm >> 1) * 8]);
    bab[0] = s2u(&Bs[(wn +      lr + (lm >> 1) * 8) * 312 + (lm & 1) * 8]);
    bab[1] = s2u(&Bs[(wn + 16 + lr + (lm >> 1) * 8) * 312 + (lm & 1) * 8]);

    float C[4][4][4];
    #pragma unroll
    for (int a = 0; a < 4; a++)
        #pragma unroll
        for (int b2 = 0; b2 < 4; b2++)
            #pragma unroll
            for (int c = 0; c < 4; c++) C[a][b2][c] = 0.f;

    #pragma unroll 2
    for (int ks = 0; ks < 19; ks++) {
        uint32_t B8[8];
        ldsm4(B8, bab[0] + ks * 32);
        ldsm4(B8 + 4, bab[1] + ks * 32);
        #pragma unroll
        for (int mo = 0; mo < 4; mo++) {
            uint32_t A4[4];
            ldsm4(A4, aab[mo] + ks * 32);
            mma16816(C[mo][0], A4, B8 + 0);
            mma16816(C[mo][1], A4, B8 + 2);
            mma16816(C[mo][2], A4, B8 + 4);
            mma16816(C[mo][3], A4, B8 + 6);
        }
    }
    __syncthreads();   // done reading As/Bs; reuse As region for C staging

    // stage C tile (+bias) in SMEM: 128 rows x 68 uint32 (pitch-68)
    uint32_t* Cs = reinterpret_cast<uint32_t*>(smA);
    #pragma unroll
    for (int mo = 0; mo < 4; mo++) {
        #pragma unroll
        for (int no = 0; no < 4; no++) {
            int gcol = n0 + wn + no * 8 + 2 * tq;
            float b0 = bias[gcol], b1v = bias[gcol + 1];
            int r1 = wm + mo * 16 + g;
            int c = (wn >> 1) + no * 4 + tq;
            Cs[r1 * 68 + c]       = pack_bf2(C[mo][no][0] + b0, C[mo][no][1] + b1v);
            Cs[(r1 + 8) * 68 + c] = pack_bf2(C[mo][no][2] + b0, C[mo][no][3] + b1v);
        }
    }
    __syncthreads();

    // coalesced write-out: warp covers 2 rows x 256B
    {
        int r = tid >> 4, c16 = tid & 15;
        #pragma unroll
        for (int p = 0; p < 8; p++) {
            int row = p * 16 + r;
            int m = m0 + row;
            int t = m & 511, bb = m >> 9;
            uint4 v = *reinterpret_cast<uint4*>(&Cs[row * 68 + c16 * 4]);
            *reinterpret_cast<uint4*>(
                &d_xg[((size_t)(t * 64 + bb)) * 2048 + n0 + c16 * 8]) = v;
        }
    }
}

// ---------------- launch 3: recurrence, 16-CTA clusters + DSMEM exchange -----
// Grid: 64 CTAs = 4 clusters (batch-groups of 16 batches) x 16 unit-CTAs.
// Per CTA/step: g[16,128] = hs[16,512] @ Ws[128,512]^T ; epilogue stages its
// 16x32 h-slice locally, then pushes it to 15 peers as 16B DSMEM stores.
// SMEM: Ws 128x520 bf16 (133120) | hs 2 x 16x520 bf16 (33280) |
//       gf 128x17 f32 (8704) | maskS 256 u32 (1024)  -> 176128 B
__global__ void __launch_bounds__(256, 1) k_recur() {
    extern __shared__ char sm[];
    bf16* Ws  = reinterpret_cast<bf16*>(sm);
    bf16* hsb = reinterpret_cast<bf16*>(sm + 133120);   // hsb + par*8320 elems
    float* gf = reinterpret_cast<float*>(sm + 166400);
    uint32_t* maskS = reinterpret_cast<uint32_t*>(sm + 175104);

    int tid = threadIdx.x, cta = blockIdx.x;
    int bg = cta >> 4;
    uint32_t ug;
    asm("mov.u32 %0, %%cluster_ctarank;" : "=r"(ug));
    int b0 = bg * 16;
    int gu0 = (int)ug * 32;

    // Ws fill: 128 n-rows (gate = n>>5, unit = gu0 + (n&31)) x K=512
    for (int i = tid; i < 128 * 512; i += 256) {
        int n = i & 127, k = i >> 7;
        Ws[n * 520 + k] = d_WhB[k * 2048 + (n >> 5) * 512 + gu0 + (n & 31)];
    }
    // mask words for this group's 16 batches
    {
        int lb = tid >> 4, w2 = tid & 15;
        maskS[tid] = d_maskB[(b0 + lb) * 16 + w2];
    }
    // zero both hs buffers (h0 = 0)
    for (int i = tid; i < 2080; i += 256)
        reinterpret_cast<uint4*>(hsb)[i] = make_uint4(0u, 0u, 0u, 0u);
    __syncthreads();
    asm volatile("barrier.cluster.arrive.aligned;" ::: "memory");
    asm volatile("barrier.cluster.wait.aligned;" ::: "memory");

    int w = tid >> 5, lane = tid & 31, g = lane >> 2, tq = lane & 3;
    int lr = lane & 7, lm = lane >> 3;
    uint32_t a_base0 = s2u(&hsb[(lr + (lm & 1) * 8) * 520 + (lm >> 1) * 8]);
    uint32_t b_base = s2u(&Ws[(w * 16 + lr + (lm >> 1) * 8) * 520 + (lm & 1) * 8]);

    int lb = tid >> 4, up = tid & 15;       // epilogue: batch lb, units 2up,2up+1
    float cst[2] = {0.f, 0.f};

    for (int t = 0; t < 512; t++) {
        int par = t & 1;

        // xg prefetch: one uint32 per gate (units 2up, 2up+1), consumed post-MMA
        const bf16* xr = d_xg + (size_t)t * 131072 + (b0 + lb) * 2048 + gu0 + 2 * up;
        uint32_t xq[4];
        xq[0] = __ldcg(reinterpret_cast<const uint32_t*>(xr));
        xq[1] = __ldcg(reinterpret_cast<const uint32_t*>(xr + 512));
        xq[2] = __ldcg(reinterpret_cast<const uint32_t*>(xr + 1024));
        xq[3] = __ldcg(reinterpret_cast<const uint32_t*>(xr + 1536));

        // MMA: h already resident in hs[par] (DSMEM-delivered)
        uint32_t ab = a_base0 + par * 16640;
        float C0[4] = {0.f, 0.f, 0.f, 0.f};
        float C1[4] = {0.f, 0.f, 0.f, 0.f};
        #pragma unroll 8
        for (int ks = 0; ks < 32; ks++) {
            uint32_t A4[4], B4[4];
            ldsm4(A4, ab + ks * 32);
            ldsm4(B4, b_base + ks * 32);
            mma16816(C0, A4, B4);
            mma16816(C1, A4, B4 + 2);
        }
        {
            int nb = w * 16 + 2 * tq;
            gf[(nb) * 17 + g]         = C0[0];
            gf[(nb + 1) * 17 + g]     = C0[1];
            gf[(nb) * 17 + g + 8]     = C0[2];
            gf[(nb + 1) * 17 + g + 8] = C0[3];
            gf[(nb + 8) * 17 + g]         = C1[0];
            gf[(nb + 9) * 17 + g]         = C1[1];
            gf[(nb + 8) * 17 + g + 8]     = C1[2];
            gf[(nb + 9) * 17 + g + 8]     = C1[3];
        }
        __syncthreads();

        // epilogue: 2 adjacent units for one batch, fully in registers
        bool act = (maskS[lb * 16 + (t >> 5)] >> (t & 31)) & 1u;
        const bf16* xb = reinterpret_cast<const bf16*>(xq);
        bf16 hov[2];
        #pragma unroll
        for (int j = 0; j < 2; j++) {
            int u = 2 * up + j;
            float gi  = gf[(u) * 17 + lb]      + __bfloat162float(xb[j]);
            float gff = gf[(32 + u) * 17 + lb] + __bfloat162float(xb[2 + j]);
            float gc  = gf[(64 + u) * 17 + lb] + __bfloat162float(xb[4 + j]);
            float go  = gf[(96 + u) * 17 + lb] + __bfloat162float(xb[6 + j]);
            float si = 1.f / (1.f + __expf(-gi));
            float sf = 1.f / (1.f + __expf(-gff));
            float so = 1.f / (1.f + __expf(-go));
            float cn = sf * cst[j] + si * fmaxf(gc, 0.f);
            float hn = so * fmaxf(cn, 0.f);
            if (act) { cst[j] = cn; hov[j] = __float2bfloat16(hn); }
            else     { hov[j] = hsb[par * 8320 + lb * 520 + gu0 + 2 * up + j]; }
        }
        uint32_t val = *reinterpret_cast<uint32_t*>(hov);

        if (t < 511) {
            int np = par ^ 1;
            // stage own slice locally (self-delivery + push source)
            *reinterpret_cast<uint32_t*>(&hsb[np * 8320 + lb * 520 + gu0 + 2 * up]) = val;
            __syncthreads();
            // push staged slice to 15 peers: 960 x 16B, <=4 per thread
            #pragma unroll
            for (int j = 0; j < 4; j++) {
                int idx = tid + j * 256;
                if (idx < 960) {
                    int peer = idx >> 6;
                    peer += (peer >= (int)ug) ? 1 : 0;
                    int q = idx & 63;
                    int row = q >> 2, c4 = q & 3;
                    const bf16* lp = &hsb[np * 8320 + row * 520 + gu0 + c4 * 8];
                    uint4 v = *reinterpret_cast<const uint4*>(lp);
                    dsm_st_u128(s2u(lp), (uint32_t)peer, v);
                }
            }
            asm volatile("barrier.cluster.arrive.aligned;" ::: "memory");
            asm volatile("barrier.cluster.wait.aligned;" ::: "memory");
        } else {
            *reinterpret_cast<uint32_t*>(&d_h[0][(b0 + lb) * 512 + gu0 + 2 * up]) = val;
        }
    }
}

// ---------------- MLP layers -------------------------------------------------
__global__ void __launch_bounds__(256) k_mlp(int mode, const float* __restrict__ bias) {
    const bf16* A; const bf16* W; bf16* out; int K;
    if (mode == 0) { A = d_h[0]; W = d_W1B; out = d_a1; K = 512; }
    else           { A = d_a1;   W = d_W2B; out = d_a2; K = 1024; }
    int tid = threadIdx.x;
    int col = blockIdx.x * 64 + (tid & 63);
    int rb = blockIdx.y * 16 + (tid >> 6);
    float acc[4] = {0.f, 0.f, 0.f, 0.f};
    for (int k = 0; k < K; k++) {
        float wv = __bfloat162float(W[k * 1024 + col]);
        #pragma unroll
        for (int j = 0; j < 4; j++)
            acc[j] += __bfloat162float(A[(rb + 4 * j) * K + k]) * wv;
    }
    float bv = bias[col];
    #pragma unroll
    for (int j = 0; j < 4; j++)
        out[(rb + 4 * j) * 1024 + col] = __float2bfloat16(fmaxf(acc[j] + bv, 0.f));
}

// ---------------- logits + softmax ------------------------------------------
__global__ void __launch_bounds__(128) k_out(const float* __restrict__ Wo,
                                             const float* __restrict__ bo,
                                             float* __restrict__ out) {
    __shared__ float red[128 * 20];
    int row = blockIdx.x, tid = threadIdx.x;
    float p[20];
    #pragma unroll
    for (int c = 0; c < 20; c++) p[c] = 0.f;
    for (int k = tid; k < 1024; k += 128) {
        float a = __bfloat162float(d_a2[row * 1024 + k]);
        #pragma unroll
        for (int c = 0; c < 20; c++) p[c] += a * Wo[k * 20 + c];
    }
    #pragma unroll
    for (int c = 0; c < 20; c++) red[tid * 20 + c] = p[c];
    __syncthreads();
    for (int s = 64; s > 0; s >>= 1) {
        if (tid < s) {
            #pragma unroll
            for (int c = 0; c < 20; c++) red[tid * 20 + c] += red[(tid + s) * 20 + c];
        }
        __syncthreads();
    }
    if (tid == 0) {
        float l[20], mx = -1e30f, ss = 0.f;
        #pragma unroll
        for (int c = 0; c < 20; c++) { l[c] = red[c] + bo[c]; mx = fmaxf(mx, l[c]); }
        #pragma unroll
        for (int c = 0; c < 20; c++) { l[c] = __expf(l[c] - mx); ss += l[c]; }
        #pragma unroll
        for (int c = 0; c < 20; c++) out[row * 20 + c] = l[c] / ss;
    }
}

// ---------------- launcher ---------------------------------------------------
extern "C" void kernel_launch(void* const* d_in, const int* in_sizes, int n_in,
                              void* d_out, int out_size) {
    const int*   tokens = (const int*)d_in[0];
    const float* emb = (const float*)d_in[1];
    const float* Wx  = (const float*)d_in[2];
    const float* Wh  = (const float*)d_in[3];
    const float* b   = (const float*)d_in[4];
    const float* W1  = (const float*)d_in[5];
    const float* b1  = (const float*)d_in[6];
    const float* W2  = (const float*)d_in[7];
    const float* b2  = (const float*)d_in[8];
    const float* Wo  = (const float*)d_in[9];
    const float* bo  = (const float*)d_in[10];
    float* out = (float*)d_out;

    cudaFuncSetAttribute(k_phaseA, cudaFuncAttributeMaxDynamicSharedMemorySize, 159744);
    cudaFuncSetAttribute(k_recur, cudaFuncAttributeMaxDynamicSharedMemorySize, 176128);
    cudaFuncSetAttribute(k_recur, cudaFuncAttributeNonPortableClusterSizeAllowed, 1);

    k_cvt_emb<<<(50000 * 38 + 255) / 256, 256>>>(emb);                          // 0
    k_cvt_rest<<<(957568 + 255) / 256, 256>>>(Wx, Wh, W1, W2, tokens);          // 1
    k_phaseA<<<dim3(16, 256), 256, 159744>>>(tokens, b);                        // 2

    {   // 16-CTA clusters: 4 clusters x 16 CTAs
        cudaLaunchConfig_t cfg = {};
        cfg.gridDim = dim3(64, 1, 1);
        cfg.blockDim = dim3(256, 1, 1);
        cfg.dynamicSmemBytes = 176128;
        cudaLaunchAttribute attrs[1];
        attrs[0].id = cudaLaunchAttributeClusterDimension;
        attrs[0].val.clusterDim.x = 16;
        attrs[0].val.clusterDim.y = 1;
        attrs[0].val.clusterDim.z = 1;
        cfg.attrs = attrs;
        cfg.numAttrs = 1;
        cudaLaunchKernelEx(&cfg, k_recur);                                      // 3
    }

    k_mlp<<<dim3(16, 4), 256>>>(0, b1);                                         // 4
    k_mlp<<<dim3(16, 4), 256>>>(1, b2);                                         // 5
    k_out<<<64, 128>>>(Wo, bo, out);                                            // 6
}

// round 16
// speedup vs baseline: 1.3680x; 1.0161x over previous
#include <cuda_runtime.h>
#include <cuda_bf16.h>
#include <stdint.h>

typedef __nv_bfloat16 bf16;

// ---------------- static device scratch (no runtime allocation) -------------
__device__ bf16 d_embB[(size_t)50000 * 304];   // padded bf16 embedding [v][304]
__device__ bf16 d_WxT[(size_t)2048 * 304];     // Wx transposed [n][304] bf16
__device__ bf16 d_WhB[512 * 2048];
__device__ bf16 d_W1B[512 * 1024];
__device__ bf16 d_W2B[1024 * 1024];
__device__ bf16 d_xg[(size_t)32768 * 2048];    // time-major [t][b][g]
__device__ bf16 d_h[2][64 * 512];              // d_h[0] = final h (for MLP)
__device__ unsigned int d_maskB[64 * 16];      // bit-packed mask [b][t/32]
__device__ bf16 d_a1[64 * 1024];
__device__ bf16 d_a2[64 * 1024];
__device__ unsigned int d_stepsG[4 * 512];     // (unused by recur now; kept for cvt)
__device__ unsigned int d_bar4[128];           // (unused by recur now; kept for cvt)

// ---------------- helpers ---------------------------------------------------
__device__ __forceinline__ uint32_t pack_bf2(float a, float b) {
    __nv_bfloat162 t = __floats2bfloat162_rn(a, b);
    return *reinterpret_cast<uint32_t*>(&t);
}

__device__ __forceinline__ void mma16816(float* c, const uint32_t* a, const uint32_t* b) {
    asm volatile(
        "mma.sync.aligned.m16n8k16.row.col.f32.bf16.bf16.f32 "
        "{%0,%1,%2,%3},{%4,%5,%6,%7},{%8,%9},{%0,%1,%2,%3};"
        : "+f"(c[0]), "+f"(c[1]), "+f"(c[2]), "+f"(c[3])
        : "r"(a[0]), "r"(a[1]), "r"(a[2]), "r"(a[3]), "r"(b[0]), "r"(b[1]));
}

__device__ __forceinline__ void ldsm4(uint32_t* r, uint32_t addr) {
    asm volatile("ldmatrix.sync.aligned.m8n8.x4.shared.b16 {%0,%1,%2,%3}, [%4];"
                 : "=r"(r[0]), "=r"(r[1]), "=r"(r[2]), "=r"(r[3]) : "r"(addr));
}

__device__ __forceinline__ uint32_t s2u(const void* p) {
    return (uint32_t)__cvta_generic_to_shared(p);
}

__device__ __forceinline__ void cp16(uint32_t dst, const void* src) {
    asm volatile("cp.async.cg.shared.global [%0], [%1], 16;" :: "r"(dst), "l"(src));
}

__device__ __forceinline__ void cp_wait_all() {
    asm volatile("cp.async.commit_group;\ncp.async.wait_group 0;" ::: "memory");
}

// vectorized 16B DSMEM store: local smem addr -> same offset in peer `rank`
__device__ __forceinline__ void dsm_st_u128(uint32_t laddr, uint32_t rank, uint4 v) {
    uint32_t pa;
    asm volatile("mapa.shared::cluster.u32 %0, %1, %2;" : "=r"(pa) : "r"(laddr), "r"(rank));
    asm volatile("st.shared::cluster.v4.u32 [%0], {%1,%2,%3,%4};"
                 :: "r"(pa), "r"(v.x), "r"(v.y), "r"(v.z), "r"(v.w) : "memory");
}

// ---------------- launch 0: vectorized embedding conversion ------------------
__global__ void k_cvt_emb(const float* __restrict__ e) {
    int i = blockIdx.x * 256 + threadIdx.x;
    if (i >= 50000 * 38) return;
    int row = i / 38, j = i - 38 * row;
    const float* src = e + (size_t)row * 300 + j * 8;
    float4 lo = *reinterpret_cast<const float4*>(src);
    float4 hi = make_float4(0.f, 0.f, 0.f, 0.f);
    if (j < 37) hi = *reinterpret_cast<const float4*>(src + 4);
    uint4 o;
    o.x = pack_bf2(lo.x, lo.y); o.y = pack_bf2(lo.z, lo.w);
    o.z = pack_bf2(hi.x, hi.y); o.w = pack_bf2(hi.z, hi.w);
    *reinterpret_cast<uint4*>(&d_embB[(size_t)row * 304 + j * 8]) = o;
}

// ---------------- launch 1: everything else (WxT, Wh/W1/W2, mask, zero) -----
__global__ void k_cvt_rest(const float* __restrict__ Wx, const float* __restrict__ Wh,
                           const float* __restrict__ W1, const float* __restrict__ W2,
                           const int* __restrict__ tokens) {
    int i = blockIdx.x * 256 + threadIdx.x;
    if (i < 622592) {                       // WxT (transpose, scalar)
        int n = i / 304, k = i - 304 * n;
        d_WxT[i] = __float2bfloat16(k < 300 ? Wx[(size_t)k * 2048 + n] : 0.f);
    } else if (i < 950272) {                // Wh/W1/W2, 8 elements per thread
        int j = i - 622592;
        const float* src; bf16* dst;
        if (j < 131072)      { src = Wh + (size_t)j * 8;            dst = d_WhB + (size_t)j * 8; }
        else if (j < 196608) { src = W1 + (size_t)(j - 131072) * 8; dst = d_W1B + (size_t)(j - 131072) * 8; }
        else                 { src = W2 + (size_t)(j - 196608) * 8; dst = d_W2B + (size_t)(j - 196608) * 8; }
        float4 lo = *reinterpret_cast<const float4*>(src);
        float4 hi = *reinterpret_cast<const float4*>(src + 4);
        uint4 o;
        o.x = pack_bf2(lo.x, lo.y); o.y = pack_bf2(lo.z, lo.w);
        o.z = pack_bf2(hi.x, hi.y); o.w = pack_bf2(hi.z, hi.w);
        *reinterpret_cast<uint4*>(dst) = o;
    } else if (i < 951296) {                // bit-packed mask [b][w]
        int j = i - 950272;                 // j < 1024
        int b = j >> 4, w = j & 15;
        unsigned int bits = 0u;
        const int* tp = tokens + b * 512 + w * 32;
        #pragma unroll 8
        for (int q = 0; q < 32; q++)
            if (tp[q] != 0) bits |= (1u << q);
        d_maskB[j] = bits;
    } else if (i < 955392) {                // zero h[0]
        uint4 z = make_uint4(0u, 0u, 0u, 0u);
        reinterpret_cast<uint4*>(d_h[0])[i - 951296] = z;
    } else if (i < 957440) {                // zero group step flags (2048)
        d_stepsG[i - 955392] = 0u;
    } else if (i < 957568) {                // zero group counters (128)
        d_bar4[i - 957440] = 0u;
    }
}

// ---------------- launch 2: Phase A  xg = gather(emb)@Wx + b ----------------
__global__ void __launch_bounds__(256) k_phaseA(const int* __restrict__ tokens,
                                                const float* __restrict__ bias) {
    extern __shared__ bf16 smA[];
    bf16* As = smA;                 // 128 x 312
    bf16* Bs = smA + 128 * 312;     // 128 x 312
    __shared__ int stok[128];

    int tid = threadIdx.x;
    int n0 = blockIdx.x * 128;
    int m0 = blockIdx.y * 128;
    if (tid < 128) stok[tid] = tokens[m0 + tid];
    __syncthreads();

    {
        int row = tid >> 1, half = tid & 1;
        const bf16* sa = &d_embB[(size_t)stok[row] * 304 + half * 152];
        uint32_t da = s2u(&As[row * 312 + half * 152]);
        const bf16* sb = &d_WxT[(size_t)(n0 + row) * 304 + half * 152];
        uint32_t db = s2u(&Bs[row * 312 + half * 152]);
        #pragma unroll
        for (int j = 0; j < 19; j++) {
            cp16(da + j * 16, sa + j * 8);
            cp16(db + j * 16, sb + j * 8);
        }
        cp_wait_all();
    }
    __syncthreads();

    int w = tid >> 5, lane = tid & 31, g = lane >> 2, tq = lane & 3;
    int wm = (w >> 2) * 64;
    int wn = (w & 3) * 32;
    int lr = lane & 7, lm = lane >> 3;

    uint32_t aab[4], bab[2];
    #pragma unroll
    for (int mo = 0; mo < 4; mo++)
        aab[mo] = s2u(&As[(wm + mo * 16 + lr + (lm & 1) * 8) * 312 + (lm >> 1) * 8]);
    bab[0] = s2u(&Bs[(wn +      lr + (lm >> 1) * 8) * 312 + (lm & 1) * 8]);
    bab[1] = s2u(&Bs[(wn + 16 + lr + (lm >> 1) * 8) * 312 + (lm & 1) * 8]);

    float C[4][4][4];
    #pragma unroll
    for (int a = 0; a < 4; a++)
        #pragma unroll
        for (int b2 = 0; b2 < 4; b2++)
            #pragma unroll
            for (int c = 0; c < 4; c++) C[a][b2][c] = 0.f;

    #pragma unroll 2
    for (int ks = 0; ks < 19; ks++) {
        uint32_t B8[8];
        ldsm4(B8, bab[0] + ks * 32);
        ldsm4(B8 + 4, bab[1] + ks * 32);
        #pragma unroll
        for (int mo = 0; mo < 4; mo++) {
            uint32_t A4[4];
            ldsm4(A4, aab[mo] + ks * 32);
            mma16816(C[mo][0], A4, B8 + 0);
            mma16816(C[mo][1], A4, B8 + 2);
            mma16816(C[mo][2], A4, B8 + 4);
            mma16816(C[mo][3], A4, B8 + 6);
        }
    }
    __syncthreads();   // done reading As/Bs; reuse As region for C staging

    // stage C tile (+bias) in SMEM: 128 rows x 68 uint32 (pitch-68)
    uint32_t* Cs = reinterpret_cast<uint32_t*>(smA);
    #pragma unroll
    for (int mo = 0; mo < 4; mo++) {
        #pragma unroll
        for (int no = 0; no < 4; no++) {
            int gcol = n0 + wn + no * 8 + 2 * tq;
            float b0 = bias[gcol], b1v = bias[gcol + 1];
            int r1 = wm + mo * 16 + g;
            int c = (wn >> 1) + no * 4 + tq;
            Cs[r1 * 68 + c]       = pack_bf2(C[mo][no][0] + b0, C[mo][no][1] + b1v);
            Cs[(r1 + 8) * 68 + c] = pack_bf2(C[mo][no][2] + b0, C[mo][no][3] + b1v);
        }
    }
    __syncthreads();

    // coalesced write-out: warp covers 2 rows x 256B
    {
        int r = tid >> 4, c16 = tid & 15;
        #pragma unroll
        for (int p = 0; p < 8; p++) {
            int row = p * 16 + r;
            int m = m0 + row;
            int t = m & 511, bb = m >> 9;
            uint4 v = *reinterpret_cast<uint4*>(&Cs[row * 68 + c16 * 4]);
            *reinterpret_cast<uint4*>(
                &d_xg[((size_t)(t * 64 + bb)) * 2048 + n0 + c16 * 8]) = v;
        }
    }
}

// ---------------- launch 3: recurrence, 16-CTA clusters + DSMEM exchange -----
// Grid: 64 CTAs = 4 clusters (batch-groups of 16 batches) x 16 unit-CTAs.
// Pipelined barrier: arrive at end of step t; step t+1 issues xg prefetch
// BEFORE cluster.wait so the wait wakeup overlaps LDG issue/latency.
// SMEM: Ws 128x520 bf16 (133120) | hs 2 x 16x520 bf16 (33280) |
//       gf 128x17 f32 (8704) | maskS 256 u32 (1024)  -> 176128 B
__global__ void __launch_bounds__(256, 1) k_recur() {
    extern __shared__ char sm[];
    bf16* Ws  = reinterpret_cast<bf16*>(sm);
    bf16* hsb = reinterpret_cast<bf16*>(sm + 133120);   // hsb + par*8320 elems
    float* gf = reinterpret_cast<float*>(sm + 166400);
    uint32_t* maskS = reinterpret_cast<uint32_t*>(sm + 175104);

    int tid = threadIdx.x, cta = blockIdx.x;
    int bg = cta >> 4;
    uint32_t ug;
    asm("mov.u32 %0, %%cluster_ctarank;" : "=r"(ug));
    int b0 = bg * 16;
    int gu0 = (int)ug * 32;

    // Ws fill: 128 n-rows (gate = n>>5, unit = gu0 + (n&31)) x K=512
    for (int i = tid; i < 128 * 512; i += 256) {
        int n = i & 127, k = i >> 7;
        Ws[n * 520 + k] = d_WhB[k * 2048 + (n >> 5) * 512 + gu0 + (n & 31)];
    }
    // mask words for this group's 16 batches
    {
        int lb = tid >> 4, w2 = tid & 15;
        maskS[tid] = d_maskB[(b0 + lb) * 16 + w2];
    }
    // zero both hs buffers (h0 = 0)
    for (int i = tid; i < 2080; i += 256)
        reinterpret_cast<uint4*>(hsb)[i] = make_uint4(0u, 0u, 0u, 0u);
    __syncthreads();
    asm volatile("barrier.cluster.arrive.aligned;" ::: "memory");
    asm volatile("barrier.cluster.wait.aligned;" ::: "memory");

    int w = tid >> 5, lane = tid & 31, g = lane >> 2, tq = lane & 3;
    int lr = lane & 7, lm = lane >> 3;
    uint32_t a_base0 = s2u(&hsb[(lr + (lm & 1) * 8) * 520 + (lm >> 1) * 8]);
    uint32_t b_base = s2u(&Ws[(w * 16 + lr + (lm >> 1) * 8) * 520 + (lm & 1) * 8]);

    int lb = tid >> 4, up = tid & 15;       // epilogue: batch lb, units 2up,2up+1
    float cst[2] = {0.f, 0.f};

    for (int t = 0; t < 512; t++) {
        int par = t & 1;

        // xg prefetch FIRST: independent of the cluster barrier
        const bf16* xr = d_xg + (size_t)t * 131072 + (b0 + lb) * 2048 + gu0 + 2 * up;
        uint32_t xq[4];
        xq[0] = __ldcg(reinterpret_cast<const uint32_t*>(xr));
        xq[1] = __ldcg(reinterpret_cast<const uint32_t*>(xr + 512));
        xq[2] = __ldcg(reinterpret_cast<const uint32_t*>(xr + 1024));
        xq[3] = __ldcg(reinterpret_cast<const uint32_t*>(xr + 1536));

        // pipelined cluster barrier: wait for step-t h (arrive happened at t-1)
        if (t > 0)
            asm volatile("barrier.cluster.wait.aligned;" ::: "memory");

        // MMA: h resident in hs[par] (DSMEM-delivered)
        uint32_t ab = a_base0 + par * 16640;
        float C0[4] = {0.f, 0.f, 0.f, 0.f};
        float C1[4] = {0.f, 0.f, 0.f, 0.f};
        #pragma unroll 16
        for (int ks = 0; ks < 32; ks++) {
            uint32_t A4[4], B4[4];
            ldsm4(A4, ab + ks * 32);
            ldsm4(B4, b_base + ks * 32);
            mma16816(C0, A4, B4);
            mma16816(C1, A4, B4 + 2);
        }
        {
            int nb = w * 16 + 2 * tq;
            gf[(nb) * 17 + g]         = C0[0];
            gf[(nb + 1) * 17 + g]     = C0[1];
            gf[(nb) * 17 + g + 8]     = C0[2];
            gf[(nb + 1) * 17 + g + 8] = C0[3];
            gf[(nb + 8) * 17 + g]         = C1[0];
            gf[(nb + 9) * 17 + g]         = C1[1];
            gf[(nb + 8) * 17 + g + 8]     = C1[2];
            gf[(nb + 9) * 17 + g + 8]     = C1[3];
        }
        __syncthreads();

        // epilogue: 2 adjacent units for one batch, fully in registers
        bool act = (maskS[lb * 16 + (t >> 5)] >> (t & 31)) & 1u;
        const bf16* xb = reinterpret_cast<const bf16*>(xq);
        bf16 hov[2];
        #pragma unroll
        for (int j = 0; j < 2; j++) {
            int u = 2 * up + j;
            float gi  = gf[(u) * 17 + lb]      + __bfloat162float(xb[j]);
            float gff = gf[(32 + u) * 17 + lb] + __bfloat162float(xb[2 + j]);
            float gc  = gf[(64 + u) * 17 + lb] + __bfloat162float(xb[4 + j]);
            float go  = gf[(96 + u) * 17 + lb] + __bfloat162float(xb[6 + j]);
            float si = 1.f / (1.f + __expf(-gi));
            float sf = 1.f / (1.f + __expf(-gff));
            float so = 1.f / (1.f + __expf(-go));
            float cn = sf * cst[j] + si * fmaxf(gc, 0.f);
            float hn = so * fmaxf(cn, 0.f);
            if (act) { cst[j] = cn; hov[j] = __float2bfloat16(hn); }
            else     { hov[j] = hsb[par * 8320 + lb * 520 + gu0 + 2 * up + j]; }
        }
        uint32_t val = *reinterpret_cast<uint32_t*>(hov);

        if (t < 511) {
            int np = par ^ 1;
            // stage own slice locally (self-delivery + push source)
            *reinterpret_cast<uint32_t*>(&hsb[np * 8320 + lb * 520 + gu0 + 2 * up]) = val;
            __syncthreads();
            // push staged slice to 15 peers: 960 x 16B, <=4 per thread
            #pragma unroll
            for (int j = 0; j < 4; j++) {
                int idx = tid + j * 256;
                if (idx < 960) {
                    int peer = idx >> 6;
                    peer += (peer >= (int)ug) ? 1 : 0;
                    int q = idx & 63;
                    int row = q >> 2, c4 = q & 3;
                    const bf16* lp = &hsb[np * 8320 + row * 520 + gu0 + c4 * 8];
                    uint4 v = *reinterpret_cast<const uint4*>(lp);
                    dsm_st_u128(s2u(lp), (uint32_t)peer, v);
                }
            }
            asm volatile("barrier.cluster.arrive.aligned;" ::: "memory");
        } else {
            *reinterpret_cast<uint32_t*>(&d_h[0][(b0 + lb) * 512 + gu0 + 2 * up]) = val;
        }
    }
}

// ---------------- MLP layers -------------------------------------------------
__global__ void __launch_bounds__(256) k_mlp(int mode, const float* __restrict__ bias) {
    const bf16* A; const bf16* W; bf16* out; int K;
    if (mode == 0) { A = d_h[0]; W = d_W1B; out = d_a1; K = 512; }
    else           { A = d_a1;   W = d_W2B; out = d_a2; K = 1024; }
    int tid = threadIdx.x;
    int col = blockIdx.x * 64 + (tid & 63);
    int rb = blockIdx.y * 16 + (tid >> 6);
    float acc[4] = {0.f, 0.f, 0.f, 0.f};
    for (int k = 0; k < K; k++) {
        float wv = __bfloat162float(W[k * 1024 + col]);
        #pragma unroll
        for (int j = 0; j < 4; j++)
            acc[j] += __bfloat162float(A[(rb + 4 * j) * K + k]) * wv;
    }
    float bv = bias[col];
    #pragma unroll
    for (int j = 0; j < 4; j++)
        out[(rb + 4 * j) * 1024 + col] = __float2bfloat16(fmaxf(acc[j] + bv, 0.f));
}

// ---------------- logits + softmax ------------------------------------------
__global__ void __launch_bounds__(128) k_out(const float* __restrict__ Wo,
                                             const float* __restrict__ bo,
                                             float* __restrict__ out) {
    __shared__ float red[128 * 20];
    int row = blockIdx.x, tid = threadIdx.x;
    float p[20];
    #pragma unroll
    for (int c = 0; c < 20; c++) p[c] = 0.f;
    for (int k = tid; k < 1024; k += 128) {
        float a = __bfloat162float(d_a2[row * 1024 + k]);
        #pragma unroll
        for (int c = 0; c < 20; c++) p[c] += a * Wo[k * 20 + c];
    }
    #pragma unroll
    for (int c = 0; c < 20; c++) red[tid * 20 + c] = p[c];
    __syncthreads();
    for (int s = 64; s > 0; s >>= 1) {
        if (tid < s) {
            #pragma unroll
            for (int c = 0; c < 20; c++) red[tid * 20 + c] += red[(tid + s) * 20 + c];
        }
        __syncthreads();
    }
    if (tid == 0) {
        float l[20], mx = -1e30f, ss = 0.f;
        #pragma unroll
        for (int c = 0; c < 20; c++) { l[c] = red[c] + bo[c]; mx = fmaxf(mx, l[c]); }
        #pragma unroll
        for (int c = 0; c < 20; c++) { l[c] = __expf(l[c] - mx); ss += l[c]; }
        #pragma unroll
        for (int c = 0; c < 20; c++) out[row * 20 + c] = l[c] / ss;
    }
}

// ---------------- launcher ---------------------------------------------------
extern "C" void kernel_launch(void* const* d_in, const int* in_sizes, int n_in,
                              void* d_out, int out_size) {
    const int*   tokens = (const int*)d_in[0];
    const float* emb = (const float*)d_in[1];
    const float* Wx  = (const float*)d_in[2];
    const float* Wh  = (const float*)d_in[3];
    const float* b   = (const float*)d_in[4];
    const float* W1  = (const float*)d_in[5];
    const float* b1  = (const float*)d_in[6];
    const float* W2  = (const float*)d_in[7];
    const float* b2  = (const float*)d_in[8];
    const float* Wo  = (const float*)d_in[9];
    const float* bo  = (const float*)d_in[10];
    float* out = (float*)d_out;

    cudaFuncSetAttribute(k_phaseA, cudaFuncAttributeMaxDynamicSharedMemorySize, 159744);
    cudaFuncSetAttribute(k_recur, cudaFuncAttributeMaxDynamicSharedMemorySize, 176128);
    cudaFuncSetAttribute(k_recur, cudaFuncAttributeNonPortableClusterSizeAllowed, 1);

    k_cvt_emb<<<(50000 * 38 + 255) / 256, 256>>>(emb);                          // 0
    k_cvt_rest<<<(957568 + 255) / 256, 256>>>(Wx, Wh, W1, W2, tokens);          // 1
    k_phaseA<<<dim3(16, 256), 256, 159744>>>(tokens, b);                        // 2

    {   // 16-CTA clusters: 4 clusters x 16 CTAs
        cudaLaunchConfig_t cfg = {};
        cfg.gridDim = dim3(64, 1, 1);
        cfg.blockDim = dim3(256, 1, 1);
        cfg.dynamicSmemBytes = 176128;
        cudaLaunchAttribute attrs[1];
        attrs[0].id = cudaLaunchAttributeClusterDimension;
        attrs[0].val.clusterDim.x = 16;
        attrs[0].val.clusterDim.y = 1;
        attrs[0].val.clusterDim.z = 1;
        cfg.attrs = attrs;
        cfg.numAttrs = 1;
        cudaLaunchKernelEx(&cfg, k_recur);                                      // 3
    }

    k_mlp<<<dim3(16, 4), 256>>>(0, b1);                                         // 4
    k_mlp<<<dim3(16, 4), 256>>>(1, b2);                                         // 5
    k_out<<<64, 128>>>(Wo, bo, out);                                            // 6
}